// round 1
// baseline (speedup 1.0000x reference)
#include <cuda_runtime.h>
#include <cuda_bf16.h>
#include <math.h>

#define N_DRUGS 4096
#define N_GENE  5414
#define N_KG    9510
#define N_MOL   131072
#define E_MOL_C 524288
#define E_KG_C  524288
#define R_REL   8
#define MLP_IN  1024
#define MLP_H   512
#define DFEAT   256
#define GCN_IN  64
#define GCN_H   128
#define DIM1    256
#define DIM2    128
#define DIM3    64
#define EPSV    1e-5f

// ---------------- scratch (device globals; no allocation allowed) ----------------
__device__ __align__(16) float g_h1[N_DRUGS * MLP_H];       // fp hidden
__device__ __align__(16) float g_fp[N_DRUGS * DFEAT];       // fp branch out
__device__ __align__(16) float g_bufA[(long)N_MOL * DFEAT]; // mol h
__device__ __align__(16) float g_bufB[(long)N_MOL * DFEAT]; // mol out / g
__device__ __align__(16) float g_dinv[N_MOL];
__device__ __align__(16) float g_pool[N_DRUGS * DFEAT];
__device__ __align__(16) float g_pcnt[N_DRUGS];
__device__ __align__(16) float g_xkg[N_KG * DFEAT];         // kg features / x2
__device__ __align__(16) float g_hr[(long)R_REL * N_KG * DFEAT]; // per-relation h
__device__ __align__(16) float g_agg[N_KG * DFEAT];         // rgcn1 out / x1
__device__ __align__(16) float g_cnt[R_REL * N_KG];
__device__ __align__(16) float g_x3[N_KG * DIM3];
__device__ __align__(16) float g_stats[4 * 512];            // colsum|colsq|mean|rstd

// ---------------- utility kernels ----------------
__global__ void zero_kernel(float* p, long n) {
    long i = (long)blockIdx.x * blockDim.x + threadIdx.x;
    if (i < n) p[i] = 0.0f;
}

__global__ void copy_kernel(float* dst, const float* src, long n) {
    long i = (long)blockIdx.x * blockDim.x + threadIdx.x;
    if (i < n) dst[i] = src[i];
}

// ---------------- SGEMM: C[M,N] = A[M,K] @ B[K,N], row-major, optional batch ----------------
__global__ void sgemm_k(const float* __restrict__ A, const float* __restrict__ B,
                        float* __restrict__ C, int M, int N, int K,
                        long strideB, long strideC) {
    const int BM = 64, BN = 64, BK = 16;
    const float* Bp = B + (long)blockIdx.z * strideB;
    float* Cp = C + (long)blockIdx.z * strideC;
    __shared__ float As[BK][BM + 4];
    __shared__ float Bs[BK][BN];
    int tid = threadIdx.x;
    int row0 = blockIdx.y * BM;
    int col0 = blockIdx.x * BN;
    int tr = (tid / 16) * 4;
    int tc = (tid % 16) * 4;
    float acc[4][4] = {};
    int aRow = tid >> 2;            // 0..63
    int aCol = (tid & 3) << 2;      // 0,4,8,12
    int bRow = tid >> 4;            // 0..15
    int bCol = (tid & 15) << 2;     // 0..60
    for (int k0 = 0; k0 < K; k0 += BK) {
        int gr = row0 + aRow;
        float4 va = make_float4(0.f, 0.f, 0.f, 0.f);
        if (gr < M) va = *(const float4*)(A + (long)gr * K + k0 + aCol);
        As[aCol + 0][aRow] = va.x; As[aCol + 1][aRow] = va.y;
        As[aCol + 2][aRow] = va.z; As[aCol + 3][aRow] = va.w;
        int gc = col0 + bCol;
        float4 vb = make_float4(0.f, 0.f, 0.f, 0.f);
        if (gc < N) vb = *(const float4*)(Bp + (long)(k0 + bRow) * N + gc);
        *(float4*)&Bs[bRow][bCol] = vb;
        __syncthreads();
#pragma unroll
        for (int kk = 0; kk < BK; kk++) {
            float a[4], b[4];
#pragma unroll
            for (int i = 0; i < 4; i++) a[i] = As[kk][tr + i];
#pragma unroll
            for (int j = 0; j < 4; j++) b[j] = Bs[kk][tc + j];
#pragma unroll
            for (int i = 0; i < 4; i++)
#pragma unroll
                for (int j = 0; j < 4; j++) acc[i][j] += a[i] * b[j];
        }
        __syncthreads();
    }
#pragma unroll
    for (int i = 0; i < 4; i++) {
        int gr = row0 + tr + i;
        if (gr < M) {
#pragma unroll
            for (int j = 0; j < 4; j++) {
                int gc = col0 + tc + j;
                if (gc < N) Cp[(long)gr * N + gc] = acc[i][j];
            }
        }
    }
}

// ---------------- BatchNorm (per-column over rows), fused relu on apply ----------------
__global__ void bn_partial(const float* __restrict__ X, int M, int F,
                           float* __restrict__ colsum, float* __restrict__ colsq) {
    float s0 = 0.f, s1 = 0.f, q0 = 0.f, q1 = 0.f;
    int f0 = threadIdx.x, f1 = threadIdx.x + 256;
    for (int r = blockIdx.x; r < M; r += gridDim.x) {
        const float* row = X + (long)r * F;
        if (f0 < F) { float v = row[f0]; s0 += v; q0 += v * v; }
        if (f1 < F) { float v = row[f1]; s1 += v; q1 += v * v; }
    }
    if (f0 < F) { atomicAdd(&colsum[f0], s0); atomicAdd(&colsq[f0], q0); }
    if (f1 < F) { atomicAdd(&colsum[f1], s1); atomicAdd(&colsq[f1], q1); }
}

__global__ void bn_finalize(int M, int F, const float* __restrict__ colsum,
                            const float* __restrict__ colsq,
                            float* __restrict__ mean, float* __restrict__ rstd) {
    int f = blockIdx.x * blockDim.x + threadIdx.x;
    if (f < F) {
        float m = colsum[f] / (float)M;
        float v = colsq[f] / (float)M - m * m;
        mean[f] = m;
        rstd[f] = rsqrtf(fmaxf(v, 0.0f) + EPSV);
    }
}

__global__ void bn_apply_relu(float* __restrict__ X, long total, int F,
                              const float* __restrict__ mean, const float* __restrict__ rstd) {
    long i = (long)blockIdx.x * blockDim.x + threadIdx.x;
    if (i < total) {
        int f = (int)(i % F);
        float v = (X[i] - mean[f]) * rstd[f];
        X[i] = v > 0.f ? v : 0.f;
    }
}

// ---------------- GCN pieces ----------------
__global__ void deg_init(float* deg, int n) {
    int i = blockIdx.x * blockDim.x + threadIdx.x;
    if (i < n) deg[i] = 1.0f;  // self loop
}
__global__ void deg_count(float* deg, const int* __restrict__ dst, int E) {
    int e = blockIdx.x * blockDim.x + threadIdx.x;
    if (e < E) atomicAdd(&deg[dst[e]], 1.0f);
}
__global__ void deg_fin(float* dinv, int n) {
    int i = blockIdx.x * blockDim.x + threadIdx.x;
    if (i < n) dinv[i] = rsqrtf(dinv[i]);
}
__global__ void gcn_self(float* __restrict__ out, const float* __restrict__ h,
                         const float* __restrict__ dinv, long total, int logF) {
    long idx = (long)blockIdx.x * blockDim.x + threadIdx.x;
    if (idx < total) {
        int i = (int)(idx >> logF);
        float di = dinv[i];
        out[idx] = h[idx] * di * di;
    }
}
__global__ void gcn_scatter(float* __restrict__ out, const float* __restrict__ h,
                            const int* __restrict__ src, const int* __restrict__ dst,
                            const float* __restrict__ dinv, int E, int logF) {
    long idx = (long)blockIdx.x * blockDim.x + threadIdx.x;
    long total = (long)E << logF;
    if (idx >= total) return;
    int e = (int)(idx >> logF);
    int f = (int)(idx & ((1 << logF) - 1));
    int s = src[e], d = dst[e];
    float nrm = dinv[s] * dinv[d];
    atomicAdd(out + ((long)d << logF) + f, h[((long)s << logF) + f] * nrm);
}

// ---------------- pooling ----------------
__global__ void pool_add(float* __restrict__ pool, const float* __restrict__ g,
                         const int* __restrict__ batch, long total) {
    long idx = (long)blockIdx.x * blockDim.x + threadIdx.x;
    if (idx < total) {
        int i = (int)(idx >> 8);
        int f = (int)(idx & 255);
        atomicAdd(pool + (long)batch[i] * DFEAT + f, g[idx]);
    }
}
__global__ void pool_cnt(float* __restrict__ cnt, const int* __restrict__ batch, int n) {
    int i = blockIdx.x * blockDim.x + threadIdx.x;
    if (i < n) atomicAdd(&cnt[batch[i]], 1.0f);
}
__global__ void pool_div(float* __restrict__ pool, const float* __restrict__ cnt, long total) {
    long idx = (long)blockIdx.x * blockDim.x + threadIdx.x;
    if (idx < total) {
        int n = (int)(idx >> 8);
        pool[idx] = pool[idx] / fmaxf(cnt[n], 1.0f);
    }
}

// ---------------- attention fusion ----------------
__global__ void att_kernel(const float* __restrict__ go, const float* __restrict__ fp,
                           const float* __restrict__ w1, const float* __restrict__ b1,
                           const float* __restrict__ w2, float* __restrict__ xkg,
                           float* __restrict__ beta_out) {
    int n = blockIdx.x;
    int tid = threadIdx.x;  // 128
    __shared__ float z0[256], z1[256];
    __shared__ float red0[4], red1[4];
    __shared__ float bsh[2];
    for (int i = tid; i < 256; i += 128) {
        z0[i] = go[(long)n * 256 + i];
        z1[i] = fp[(long)n * 256 + i];
    }
    __syncthreads();
    float s0 = 0.f, s1 = 0.f;
#pragma unroll 4
    for (int d = 0; d < 256; d++) {
        float w = w1[d * 128 + tid];
        s0 += z0[d] * w;
        s1 += z1[d] * w;
    }
    float bb = b1[tid], ww = w2[tid];
    float t0 = tanhf(s0 + bb) * ww;
    float t1 = tanhf(s1 + bb) * ww;
#pragma unroll
    for (int o = 16; o > 0; o >>= 1) {
        t0 += __shfl_down_sync(0xffffffffu, t0, o);
        t1 += __shfl_down_sync(0xffffffffu, t1, o);
    }
    int wid = tid >> 5, lid = tid & 31;
    if (lid == 0) { red0[wid] = t0; red1[wid] = t1; }
    __syncthreads();
    if (tid == 0) {
        float a0 = red0[0] + red0[1] + red0[2] + red0[3];
        float a1 = red1[0] + red1[1] + red1[2] + red1[3];
        float m = fmaxf(a0, a1);
        float e0 = expf(a0 - m), e1 = expf(a1 - m);
        float inv = 1.0f / (e0 + e1);
        bsh[0] = e0 * inv; bsh[1] = e1 * inv;
        beta_out[2 * n] = e0 * inv;
        beta_out[2 * n + 1] = e1 * inv;
    }
    __syncthreads();
    float b0v = bsh[0], b1v = bsh[1];
    for (int i = tid; i < 256; i += 128)
        xkg[(long)n * 256 + i] = b0v * z0[i] + b1v * z1[i];
}

// ---------------- RGCN pieces ----------------
__global__ void rgcn_cnt(float* __restrict__ cnt, const int* __restrict__ et,
                         const int* __restrict__ dst, int E) {
    int e = blockIdx.x * blockDim.x + threadIdx.x;
    if (e < E) atomicAdd(&cnt[et[e] * N_KG + dst[e]], 1.0f);
}
__global__ void rgcn_scatter(float* __restrict__ agg, const float* __restrict__ hr,
                             const int* __restrict__ src, const int* __restrict__ dst,
                             const int* __restrict__ et, const float* __restrict__ cnt,
                             int E, int logF) {
    long idx = (long)blockIdx.x * blockDim.x + threadIdx.x;
    long total = (long)E << logF;
    if (idx >= total) return;
    int e = (int)(idx >> logF);
    int f = (int)(idx & ((1 << logF) - 1));
    int r = et[e];
    int s = src[e], d = dst[e];
    float nrm = 1.0f / fmaxf(cnt[r * N_KG + d], 1.0f);
    atomicAdd(agg + ((long)d << logF) + f, hr[(((long)r * N_KG + s) << logF) + f] * nrm);
}

// ---------------- final head: lin2 + log_softmax ----------------
__global__ void lin2_k(const float* __restrict__ x, const float* __restrict__ w,
                       const float* __restrict__ b, float* __restrict__ out) {
    int row = blockIdx.x * blockDim.x + threadIdx.x;
    if (row >= N_KG) return;
    float l0 = b[0], l1 = b[1];
    const float* xr = x + (long)row * 64;
#pragma unroll
    for (int d = 0; d < 64; d++) {
        float v = xr[d];
        l0 += v * w[2 * d];
        l1 += v * w[2 * d + 1];
    }
    float m = fmaxf(l0, l1);
    float lse = m + logf(expf(l0 - m) + expf(l1 - m));
    out[2 * row] = l0 - lse;
    out[2 * row + 1] = l1 - lse;
}

// ---------------- host driver ----------------
static inline int cdiv(long a, long b) { return (int)((a + b - 1) / b); }

static void run_bn(float* X, int M, int F, float* stats) {
    float* colsum = stats;
    float* colsq = stats + 512;
    float* mean = stats + 1024;
    float* rstd = stats + 1536;
    zero_kernel<<<cdiv(1024, 256), 256>>>(stats, 1024);
    int grid = M < 1184 ? M : 1184;
    bn_partial<<<grid, 256>>>(X, M, F, colsum, colsq);
    bn_finalize<<<cdiv(F, 128), 128>>>(M, F, colsum, colsq, mean, rstd);
    long total = (long)M * F;
    bn_apply_relu<<<cdiv(total, 256), 256>>>(X, total, F, mean, rstd);
}

extern "C" void kernel_launch(void* const* d_in, const int* in_sizes, int n_in,
                              void* d_out, int out_size) {
    const float* fp_data = (const float*)d_in[0];
    const float* mol_x   = (const float*)d_in[1];
    const int*   mol_batch = (const int*)d_in[2];
    const int*   mol_ei  = (const int*)d_in[3];
    const int*   kg_ei   = (const int*)d_in[4];
    const int*   kg_et   = (const int*)d_in[5];
    const float* fp_w1   = (const float*)d_in[6];
    const float* fp_w2   = (const float*)d_in[8];
    const float* gcn_w1  = (const float*)d_in[10];
    const float* gcn_w2  = (const float*)d_in[12];
    const float* att_w1  = (const float*)d_in[14];
    const float* att_b1  = (const float*)d_in[15];
    const float* att_w2  = (const float*)d_in[16];
    const float* gene_emb = (const float*)d_in[17];
    const float* rg_w1   = (const float*)d_in[18];
    const float* rg_root1 = (const float*)d_in[19];
    const float* rg_w2   = (const float*)d_in[21];
    const float* rg_root2 = (const float*)d_in[22];
    const float* lin1_w  = (const float*)d_in[24];
    const float* lin2_w  = (const float*)d_in[26];
    const float* lin2_b  = (const float*)d_in[27];
    float* out = (float*)d_out;

    float *h1, *fpb, *bufA, *bufB, *dinv, *pool, *pcnt, *xkg, *hr, *agg, *cnt, *x3, *stats;
    cudaGetSymbolAddress((void**)&h1, g_h1);
    cudaGetSymbolAddress((void**)&fpb, g_fp);
    cudaGetSymbolAddress((void**)&bufA, g_bufA);
    cudaGetSymbolAddress((void**)&bufB, g_bufB);
    cudaGetSymbolAddress((void**)&dinv, g_dinv);
    cudaGetSymbolAddress((void**)&pool, g_pool);
    cudaGetSymbolAddress((void**)&pcnt, g_pcnt);
    cudaGetSymbolAddress((void**)&xkg, g_xkg);
    cudaGetSymbolAddress((void**)&hr, g_hr);
    cudaGetSymbolAddress((void**)&agg, g_agg);
    cudaGetSymbolAddress((void**)&cnt, g_cnt);
    cudaGetSymbolAddress((void**)&x3, g_x3);
    cudaGetSymbolAddress((void**)&stats, g_stats);

    const int* msrc = mol_ei;
    const int* mdst = mol_ei + E_MOL_C;
    const int* ksrc = kg_ei;
    const int* kdst = kg_ei + E_KG_C;

    // ---- fingerprint MLP branch (biases cancel under BN) ----
    sgemm_k<<<dim3(MLP_H / 64, N_DRUGS / 64), 256>>>(fp_data, fp_w1, h1, N_DRUGS, MLP_H, MLP_IN, 0, 0);
    run_bn(h1, N_DRUGS, MLP_H, stats);
    sgemm_k<<<dim3(DFEAT / 64, N_DRUGS / 64), 256>>>(h1, fp_w2, fpb, N_DRUGS, DFEAT, MLP_H, 0, 0);
    run_bn(fpb, N_DRUGS, DFEAT, stats);

    // ---- molecular GCN branch ----
    deg_init<<<cdiv(N_MOL, 256), 256>>>(dinv, N_MOL);
    deg_count<<<cdiv(E_MOL_C, 256), 256>>>(dinv, mdst, E_MOL_C);
    deg_fin<<<cdiv(N_MOL, 256), 256>>>(dinv, N_MOL);

    // conv1: h = mol_x @ w1  [N_MOL,128]
    sgemm_k<<<dim3(GCN_H / 64, N_MOL / 64), 256>>>(mol_x, gcn_w1, bufA, N_MOL, GCN_H, GCN_IN, 0, 0);
    {
        long tot = (long)N_MOL * GCN_H;
        gcn_self<<<cdiv(tot, 256), 256>>>(bufB, bufA, dinv, tot, 7);
        long etot = (long)E_MOL_C << 7;
        gcn_scatter<<<cdiv(etot, 256), 256>>>(bufB, bufA, msrc, mdst, dinv, E_MOL_C, 7);
    }
    run_bn(bufB, N_MOL, GCN_H, stats);

    // conv2: h = g @ w2  [N_MOL,256]
    sgemm_k<<<dim3(DFEAT / 64, N_MOL / 64), 256>>>(bufB, gcn_w2, bufA, N_MOL, DFEAT, GCN_H, 0, 0);
    {
        long tot = (long)N_MOL * DFEAT;
        gcn_self<<<cdiv(tot, 256), 256>>>(bufB, bufA, dinv, tot, 8);
        long etot = (long)E_MOL_C << 8;
        gcn_scatter<<<cdiv(etot, 256), 256>>>(bufB, bufA, msrc, mdst, dinv, E_MOL_C, 8);
    }
    run_bn(bufB, N_MOL, DFEAT, stats);

    // ---- global mean pool ----
    zero_kernel<<<cdiv((long)N_DRUGS * DFEAT, 256), 256>>>(pool, (long)N_DRUGS * DFEAT);
    zero_kernel<<<cdiv(N_DRUGS, 256), 256>>>(pcnt, N_DRUGS);
    pool_add<<<cdiv((long)N_MOL * DFEAT, 256), 256>>>(pool, bufB, mol_batch, (long)N_MOL * DFEAT);
    pool_cnt<<<cdiv(N_MOL, 256), 256>>>(pcnt, mol_batch, N_MOL);
    pool_div<<<cdiv((long)N_DRUGS * DFEAT, 256), 256>>>(pool, pcnt, (long)N_DRUGS * DFEAT);

    // ---- attention fusion -> xkg[0:N_DRUGS], beta -> out tail ----
    att_kernel<<<N_DRUGS, 128>>>(pool, fpb, att_w1, att_b1, att_w2, xkg, out + N_KG * 2);
    copy_kernel<<<cdiv((long)N_GENE * DFEAT, 256), 256>>>(xkg + (long)N_DRUGS * DFEAT, gene_emb,
                                                          (long)N_GENE * DFEAT);

    // ---- RGCN layer 1 (D=256 -> DIM1=256) ----
    sgemm_k<<<dim3(DIM1 / 64, cdiv(N_KG, 64), R_REL), 256>>>(xkg, rg_w1, hr, N_KG, DIM1, DFEAT,
                                                             (long)DFEAT * DIM1, (long)N_KG * DIM1);
    sgemm_k<<<dim3(DIM1 / 64, cdiv(N_KG, 64)), 256>>>(xkg, rg_root1, agg, N_KG, DIM1, DFEAT, 0, 0);
    zero_kernel<<<cdiv(R_REL * N_KG, 256), 256>>>(cnt, R_REL * N_KG);
    rgcn_cnt<<<cdiv(E_KG_C, 256), 256>>>(cnt, kg_et, kdst, E_KG_C);
    {
        long etot = (long)E_KG_C << 8;
        rgcn_scatter<<<cdiv(etot, 256), 256>>>(agg, hr, ksrc, kdst, kg_et, cnt, E_KG_C, 8);
    }
    run_bn(agg, N_KG, DIM1, stats);

    // ---- RGCN layer 2 (DIM1=256 -> DIM2=128) ----
    sgemm_k<<<dim3(DIM2 / 64, cdiv(N_KG, 64), R_REL), 256>>>(agg, rg_w2, hr, N_KG, DIM2, DIM1,
                                                             (long)DIM1 * DIM2, (long)N_KG * DIM2);
    sgemm_k<<<dim3(DIM2 / 64, cdiv(N_KG, 64)), 256>>>(agg, rg_root2, xkg, N_KG, DIM2, DIM1, 0, 0);
    {
        long etot = (long)E_KG_C << 7;
        rgcn_scatter<<<cdiv(etot, 256), 256>>>(xkg, hr, ksrc, kdst, kg_et, cnt, E_KG_C, 7);
    }
    run_bn(xkg, N_KG, DIM2, stats);

    // ---- lin1 + bn + relu ----
    sgemm_k<<<dim3(1, cdiv(N_KG, 64)), 256>>>(xkg, lin1_w, x3, N_KG, DIM3, DIM2, 0, 0);
    run_bn(x3, N_KG, DIM3, stats);

    // ---- lin2 + log_softmax ----
    lin2_k<<<cdiv(N_KG, 128), 128>>>(x3, lin2_w, lin2_b, out);
}

// round 3
// speedup vs baseline: 1.2683x; 1.2683x over previous
#include <cuda_runtime.h>
#include <cuda_bf16.h>
#include <math.h>

#define N_DRUGS 4096
#define N_GENE  5414
#define N_KG    9510
#define N_MOL   131072
#define E_MOL_C 524288
#define E_KG_C  524288
#define R_REL   8
#define MLP_IN  1024
#define MLP_H   512
#define DFEAT   256
#define GCN_IN  64
#define GCN_H   128
#define DIM1    256
#define DIM2    128
#define DIM3    64
#define EPSV    1e-5f

// ---------------- scratch (device globals; no allocation allowed) ----------------
__device__ __align__(16) float g_h1[N_DRUGS * MLP_H];
__device__ __align__(16) float g_fp[N_DRUGS * DFEAT];
__device__ __align__(16) float g_bufA[(long)N_MOL * DFEAT];
__device__ __align__(16) float g_bufB[(long)N_MOL * DFEAT];
__device__ __align__(16) float g_bufC[(long)N_MOL * DFEAT];
__device__ __align__(16) float g_dinv[N_MOL];
__device__ __align__(16) float g_pool[N_DRUGS * DFEAT];
__device__ __align__(16) float g_pcnt[N_DRUGS];
__device__ __align__(16) float g_xkg[N_KG * DFEAT];
__device__ __align__(16) float g_hr[(long)R_REL * N_KG * DFEAT];
__device__ __align__(16) float g_agg[N_KG * DFEAT];
__device__ __align__(16) float g_cnt[R_REL * N_KG];
__device__ __align__(16) float g_x3[N_KG * DIM3];
__device__ __align__(16) float g_stats[4 * 512];

// ---------------- utility kernels ----------------
__global__ void zero_kernel(float* p, long n) {
    long i = (long)blockIdx.x * blockDim.x + threadIdx.x;
    if (i < n) p[i] = 0.0f;
}
__global__ void copy_kernel(float4* dst, const float4* src, long n4) {
    long i = (long)blockIdx.x * blockDim.x + threadIdx.x;
    if (i < n4) dst[i] = src[i];
}

// ---------------- SGEMM 128x128x16, double buffered, 8x8 per thread ----------------
// C[M,N] = A[M,K] @ B[K,N]; optional batch via blockIdx.z with strideB/strideC.
// If C2 != nullptr: also writes C2[r,c] = C[r,c] * rowscale[r]^2 (GCN self-loop fuse).
// NOTE: C2 must NOT alias A (race).
__global__ __launch_bounds__(256, 2)
void sgemm128(const float* __restrict__ A, const float* __restrict__ B,
              float* __restrict__ C, int M, int N, int K,
              long strideB, long strideC,
              float* __restrict__ C2, const float* __restrict__ rowscale) {
    const int BM = 128, BN = 128, BK = 16;
    __shared__ float As[2][BK][BM + 4];
    __shared__ float Bs[2][BK][BN];
    const float* Bp = B + (long)blockIdx.z * strideB;
    float* Cp = C + (long)blockIdx.z * strideC;
    int tid = threadIdx.x;
    int row0 = blockIdx.y * BM, col0 = blockIdx.x * BN;
    int aRow = tid >> 2;            // 0..63
    int aCol = (tid & 3) << 2;      // 0,4,8,12
    int bRow = tid >> 5;            // 0..7
    int bCol = (tid & 31) << 2;     // 0..124
    int tm = (tid >> 4) << 3;       // 0..120
    int tn = (tid & 15) << 3;       // 0..120
    float acc[8][8] = {};
    float4 ra[2], rb[2];
    int nk = K / BK;

    {
        int k0 = 0;
#pragma unroll
        for (int i = 0; i < 2; i++) {
            int gr = row0 + aRow + i * 64;
            float4 v = make_float4(0.f, 0.f, 0.f, 0.f);
            if (gr < M) v = *(const float4*)(A + (long)gr * K + k0 + aCol);
            As[0][aCol + 0][aRow + i * 64] = v.x;
            As[0][aCol + 1][aRow + i * 64] = v.y;
            As[0][aCol + 2][aRow + i * 64] = v.z;
            As[0][aCol + 3][aRow + i * 64] = v.w;
        }
#pragma unroll
        for (int i = 0; i < 2; i++) {
            int gk = k0 + bRow + i * 8;
            int gc = col0 + bCol;
            float4 v = make_float4(0.f, 0.f, 0.f, 0.f);
            if (gc < N) v = *(const float4*)(Bp + (long)gk * N + gc);
            *(float4*)&Bs[0][bRow + i * 8][bCol] = v;
        }
    }
    __syncthreads();
    int cur = 0;
    for (int t = 0; t < nk; t++) {
        if (t + 1 < nk) {
            int k0 = (t + 1) * BK;
#pragma unroll
            for (int i = 0; i < 2; i++) {
                int gr = row0 + aRow + i * 64;
                ra[i] = make_float4(0.f, 0.f, 0.f, 0.f);
                if (gr < M) ra[i] = *(const float4*)(A + (long)gr * K + k0 + aCol);
            }
#pragma unroll
            for (int i = 0; i < 2; i++) {
                int gk = k0 + bRow + i * 8;
                int gc = col0 + bCol;
                rb[i] = make_float4(0.f, 0.f, 0.f, 0.f);
                if (gc < N) rb[i] = *(const float4*)(Bp + (long)gk * N + gc);
            }
        }
#pragma unroll
        for (int kk = 0; kk < BK; kk++) {
            float a[8], b[8];
            *(float4*)&a[0] = *(float4*)&As[cur][kk][tm];
            *(float4*)&a[4] = *(float4*)&As[cur][kk][tm + 4];
            *(float4*)&b[0] = *(float4*)&Bs[cur][kk][tn];
            *(float4*)&b[4] = *(float4*)&Bs[cur][kk][tn + 4];
#pragma unroll
            for (int i = 0; i < 8; i++)
#pragma unroll
                for (int j = 0; j < 8; j++) acc[i][j] += a[i] * b[j];
        }
        if (t + 1 < nk) {
            int nb = cur ^ 1;
#pragma unroll
            for (int i = 0; i < 2; i++) {
                As[nb][aCol + 0][aRow + i * 64] = ra[i].x;
                As[nb][aCol + 1][aRow + i * 64] = ra[i].y;
                As[nb][aCol + 2][aRow + i * 64] = ra[i].z;
                As[nb][aCol + 3][aRow + i * 64] = ra[i].w;
            }
#pragma unroll
            for (int i = 0; i < 2; i++)
                *(float4*)&Bs[nb][bRow + i * 8][bCol] = rb[i];
            __syncthreads();
            cur = nb;
        }
    }
    bool fullN = (col0 + BN <= N);
#pragma unroll
    for (int i = 0; i < 8; i++) {
        int gr = row0 + tm + i;
        if (gr >= M) break;
        float* crow = Cp + (long)gr * N;
        if (fullN) {
            *(float4*)&crow[col0 + tn] = *(float4*)&acc[i][0];
            *(float4*)&crow[col0 + tn + 4] = *(float4*)&acc[i][4];
            if (C2) {
                float di = rowscale[gr];
                float s = di * di;
                float4 v0 = *(float4*)&acc[i][0], v1 = *(float4*)&acc[i][4];
                v0.x *= s; v0.y *= s; v0.z *= s; v0.w *= s;
                v1.x *= s; v1.y *= s; v1.z *= s; v1.w *= s;
                float* c2row = C2 + (long)gr * N;
                *(float4*)&c2row[col0 + tn] = v0;
                *(float4*)&c2row[col0 + tn + 4] = v1;
            }
        } else {
            float s = 0.f;
            if (C2) { float di = rowscale[gr]; s = di * di; }
#pragma unroll
            for (int j = 0; j < 8; j++) {
                int gc = col0 + tn + j;
                if (gc < N) {
                    crow[gc] = acc[i][j];
                    if (C2) C2[(long)gr * N + gc] = acc[i][j] * s;
                }
            }
        }
    }
}

// ---------------- BatchNorm ----------------
__global__ void bn_partial(const float* __restrict__ X, int M, int F,
                           float* __restrict__ colsum, float* __restrict__ colsq) {
    float s0 = 0.f, s1 = 0.f, q0 = 0.f, q1 = 0.f;
    int f0 = threadIdx.x, f1 = threadIdx.x + 256;
    for (int r = blockIdx.x; r < M; r += gridDim.x) {
        const float* row = X + (long)r * F;
        if (f0 < F) { float v = row[f0]; s0 += v; q0 += v * v; }
        if (f1 < F) { float v = row[f1]; s1 += v; q1 += v * v; }
    }
    if (f0 < F) { atomicAdd(&colsum[f0], s0); atomicAdd(&colsq[f0], q0); }
    if (f1 < F) { atomicAdd(&colsum[f1], s1); atomicAdd(&colsq[f1], q1); }
}

__global__ void bn_finalize(int M, int F, const float* __restrict__ colsum,
                            const float* __restrict__ colsq,
                            float* __restrict__ mean, float* __restrict__ rstd) {
    int f = blockIdx.x * blockDim.x + threadIdx.x;
    if (f < F) {
        float m = colsum[f] / (float)M;
        float v = colsq[f] / (float)M - m * m;
        mean[f] = m;
        rstd[f] = rsqrtf(fmaxf(v, 0.0f) + EPSV);
    }
}

__global__ void bn_apply_relu4(float4* __restrict__ X, long total4, int F4,
                               const float* __restrict__ mean, const float* __restrict__ rstd) {
    long i = (long)blockIdx.x * blockDim.x + threadIdx.x;
    if (i < total4) {
        int f4 = (int)(i % F4);
        int f = f4 * 4;
        float4 v = X[i];
        v.x = fmaxf((v.x - mean[f + 0]) * rstd[f + 0], 0.f);
        v.y = fmaxf((v.y - mean[f + 1]) * rstd[f + 1], 0.f);
        v.z = fmaxf((v.z - mean[f + 2]) * rstd[f + 2], 0.f);
        v.w = fmaxf((v.w - mean[f + 3]) * rstd[f + 3], 0.f);
        X[i] = v;
    }
}

// ---------------- GCN pieces ----------------
__global__ void deg_init(float* deg, int n) {
    int i = blockIdx.x * blockDim.x + threadIdx.x;
    if (i < n) deg[i] = 1.0f;
}
__global__ void deg_count(float* deg, const int* __restrict__ dst, int E) {
    int e = blockIdx.x * blockDim.x + threadIdx.x;
    if (e < E) atomicAdd(&deg[dst[e]], 1.0f);
}
__global__ void deg_fin(float* dinv, int n) {
    int i = blockIdx.x * blockDim.x + threadIdx.x;
    if (i < n) dinv[i] = rsqrtf(dinv[i]);
}
__global__ void gcn_scatter4(float* __restrict__ out, const float* __restrict__ h,
                             const int* __restrict__ src, const int* __restrict__ dst,
                             const float* __restrict__ dinv, int E, int logF4) {
    long idx = (long)blockIdx.x * blockDim.x + threadIdx.x;
    long total = (long)E << logF4;
    if (idx >= total) return;
    int e = (int)(idx >> logF4);
    int f4 = (int)(idx & ((1 << logF4) - 1));
    int s = src[e], d = dst[e];
    float nrm = dinv[s] * dinv[d];
    float4 v = *(const float4*)(h + (((long)s << logF4) + f4) * 4);
    float* o = out + (((long)d << logF4) + f4) * 4;
    atomicAdd(o + 0, v.x * nrm);
    atomicAdd(o + 1, v.y * nrm);
    atomicAdd(o + 2, v.z * nrm);
    atomicAdd(o + 3, v.w * nrm);
}

// ---------------- pooling ----------------
__global__ void pool_add4(float* __restrict__ pool, const float* __restrict__ g,
                          const int* __restrict__ batch, long total4) {
    long idx = (long)blockIdx.x * blockDim.x + threadIdx.x;
    if (idx >= total4) return;
    int i = (int)(idx >> 6);   // DFEAT/4 = 64 float4 per node
    int f4 = (int)(idx & 63);
    float4 v = *(const float4*)(g + ((long)i * DFEAT) + f4 * 4);
    float* p = pool + (long)batch[i] * DFEAT + f4 * 4;
    atomicAdd(p + 0, v.x);
    atomicAdd(p + 1, v.y);
    atomicAdd(p + 2, v.z);
    atomicAdd(p + 3, v.w);
}
__global__ void pool_cnt(float* __restrict__ cnt, const int* __restrict__ batch, int n) {
    int i = blockIdx.x * blockDim.x + threadIdx.x;
    if (i < n) atomicAdd(&cnt[batch[i]], 1.0f);
}

// ---------------- attention fusion (pool mean fused in) ----------------
__global__ void att_kernel(const float* __restrict__ pool, const float* __restrict__ pcnt,
                           const float* __restrict__ fp,
                           const float* __restrict__ w1, const float* __restrict__ b1,
                           const float* __restrict__ w2, float* __restrict__ xkg,
                           float* __restrict__ beta_out) {
    int n = blockIdx.x;
    int tid = threadIdx.x;  // 128
    __shared__ float z0[256], z1[256];
    __shared__ float red0[4], red1[4];
    __shared__ float bsh[2];
    float invc = 1.0f / fmaxf(pcnt[n], 1.0f);
    for (int i = tid; i < 256; i += 128) {
        z0[i] = pool[(long)n * 256 + i] * invc;
        z1[i] = fp[(long)n * 256 + i];
    }
    __syncthreads();
    float s0 = 0.f, s1 = 0.f;
#pragma unroll 4
    for (int d = 0; d < 256; d++) {
        float w = w1[d * 128 + tid];
        s0 += z0[d] * w;
        s1 += z1[d] * w;
    }
    float bb = b1[tid], ww = w2[tid];
    float t0 = tanhf(s0 + bb) * ww;
    float t1 = tanhf(s1 + bb) * ww;
#pragma unroll
    for (int o = 16; o > 0; o >>= 1) {
        t0 += __shfl_down_sync(0xffffffffu, t0, o);
        t1 += __shfl_down_sync(0xffffffffu, t1, o);
    }
    int wid = tid >> 5, lid = tid & 31;
    if (lid == 0) { red0[wid] = t0; red1[wid] = t1; }
    __syncthreads();
    if (tid == 0) {
        float a0 = red0[0] + red0[1] + red0[2] + red0[3];
        float a1 = red1[0] + red1[1] + red1[2] + red1[3];
        float m = fmaxf(a0, a1);
        float e0 = expf(a0 - m), e1 = expf(a1 - m);
        float inv = 1.0f / (e0 + e1);
        bsh[0] = e0 * inv; bsh[1] = e1 * inv;
        beta_out[2 * n] = e0 * inv;
        beta_out[2 * n + 1] = e1 * inv;
    }
    __syncthreads();
    float b0v = bsh[0], b1v = bsh[1];
    for (int i = tid; i < 256; i += 128)
        xkg[(long)n * 256 + i] = b0v * z0[i] + b1v * z1[i];
}

// ---------------- RGCN pieces ----------------
__global__ void rgcn_cnt(float* __restrict__ cnt, const int* __restrict__ et,
                         const int* __restrict__ dst, int E) {
    int e = blockIdx.x * blockDim.x + threadIdx.x;
    if (e < E) atomicAdd(&cnt[et[e] * N_KG + dst[e]], 1.0f);
}
__global__ void rgcn_scatter4(float* __restrict__ agg, const float* __restrict__ hr,
                              const int* __restrict__ src, const int* __restrict__ dst,
                              const int* __restrict__ et, const float* __restrict__ cnt,
                              int E, int logF4) {
    long idx = (long)blockIdx.x * blockDim.x + threadIdx.x;
    long total = (long)E << logF4;
    if (idx >= total) return;
    int e = (int)(idx >> logF4);
    int f4 = (int)(idx & ((1 << logF4) - 1));
    int r = et[e];
    int s = src[e], d = dst[e];
    float nrm = 1.0f / fmaxf(cnt[r * N_KG + d], 1.0f);
    float4 v = *(const float4*)(hr + ((((long)r * N_KG + s) << logF4) + f4) * 4);
    float* o = agg + (((long)d << logF4) + f4) * 4;
    atomicAdd(o + 0, v.x * nrm);
    atomicAdd(o + 1, v.y * nrm);
    atomicAdd(o + 2, v.z * nrm);
    atomicAdd(o + 3, v.w * nrm);
}

// ---------------- final head ----------------
__global__ void lin2_k(const float* __restrict__ x, const float* __restrict__ w,
                       const float* __restrict__ b, float* __restrict__ out) {
    int row = blockIdx.x * blockDim.x + threadIdx.x;
    if (row >= N_KG) return;
    float l0 = b[0], l1 = b[1];
    const float* xr = x + (long)row * 64;
#pragma unroll
    for (int d = 0; d < 64; d++) {
        float v = xr[d];
        l0 += v * w[2 * d];
        l1 += v * w[2 * d + 1];
    }
    float m = fmaxf(l0, l1);
    float lse = m + logf(expf(l0 - m) + expf(l1 - m));
    out[2 * row] = l0 - lse;
    out[2 * row + 1] = l1 - lse;
}

// ---------------- host driver ----------------
static inline int cdiv(long a, long b) { return (int)((a + b - 1) / b); }

static void run_bn(float* X, int M, int F, float* stats) {
    float* colsum = stats;
    float* colsq = stats + 512;
    float* mean = stats + 1024;
    float* rstd = stats + 1536;
    zero_kernel<<<4, 256>>>(stats, 1024);
    int grid = M < 1184 ? M : 1184;
    bn_partial<<<grid, 256>>>(X, M, F, colsum, colsq);
    bn_finalize<<<cdiv(F, 128), 128>>>(M, F, colsum, colsq, mean, rstd);
    long total4 = (long)M * F / 4;
    bn_apply_relu4<<<cdiv(total4, 256), 256>>>((float4*)X, total4, F / 4, mean, rstd);
}

static void gemm(const float* A, const float* B, float* C, int M, int N, int K,
                 long sB = 0, long sC = 0, int batch = 1,
                 float* C2 = nullptr, const float* rowscale = nullptr) {
    dim3 grid(cdiv(N, 128), cdiv(M, 128), batch);
    sgemm128<<<grid, 256>>>(A, B, C, M, N, K, sB, sC, C2, rowscale);
}

extern "C" void kernel_launch(void* const* d_in, const int* in_sizes, int n_in,
                              void* d_out, int out_size) {
    const float* fp_data = (const float*)d_in[0];
    const float* mol_x   = (const float*)d_in[1];
    const int*   mol_batch = (const int*)d_in[2];
    const int*   mol_ei  = (const int*)d_in[3];
    const int*   kg_ei   = (const int*)d_in[4];
    const int*   kg_et   = (const int*)d_in[5];
    const float* fp_w1   = (const float*)d_in[6];
    const float* fp_w2   = (const float*)d_in[8];
    const float* gcn_w1  = (const float*)d_in[10];
    const float* gcn_w2  = (const float*)d_in[12];
    const float* att_w1  = (const float*)d_in[14];
    const float* att_b1  = (const float*)d_in[15];
    const float* att_w2  = (const float*)d_in[16];
    const float* gene_emb = (const float*)d_in[17];
    const float* rg_w1   = (const float*)d_in[18];
    const float* rg_root1 = (const float*)d_in[19];
    const float* rg_w2   = (const float*)d_in[21];
    const float* rg_root2 = (const float*)d_in[22];
    const float* lin1_w  = (const float*)d_in[24];
    const float* lin2_w  = (const float*)d_in[26];
    const float* lin2_b  = (const float*)d_in[27];
    float* out = (float*)d_out;

    float *h1, *fpb, *bufA, *bufB, *bufC, *dinv, *pool, *pcnt, *xkg, *hr, *agg, *cnt, *x3, *stats;
    cudaGetSymbolAddress((void**)&h1, g_h1);
    cudaGetSymbolAddress((void**)&fpb, g_fp);
    cudaGetSymbolAddress((void**)&bufA, g_bufA);
    cudaGetSymbolAddress((void**)&bufB, g_bufB);
    cudaGetSymbolAddress((void**)&bufC, g_bufC);
    cudaGetSymbolAddress((void**)&dinv, g_dinv);
    cudaGetSymbolAddress((void**)&pool, g_pool);
    cudaGetSymbolAddress((void**)&pcnt, g_pcnt);
    cudaGetSymbolAddress((void**)&xkg, g_xkg);
    cudaGetSymbolAddress((void**)&hr, g_hr);
    cudaGetSymbolAddress((void**)&agg, g_agg);
    cudaGetSymbolAddress((void**)&cnt, g_cnt);
    cudaGetSymbolAddress((void**)&x3, g_x3);
    cudaGetSymbolAddress((void**)&stats, g_stats);

    const int* msrc = mol_ei;
    const int* mdst = mol_ei + E_MOL_C;
    const int* ksrc = kg_ei;
    const int* kdst = kg_ei + E_KG_C;

    // ---- fingerprint MLP branch (biases cancel under BN) ----
    gemm(fp_data, fp_w1, h1, N_DRUGS, MLP_H, MLP_IN);
    run_bn(h1, N_DRUGS, MLP_H, stats);
    gemm(h1, fp_w2, fpb, N_DRUGS, DFEAT, MLP_H);
    run_bn(fpb, N_DRUGS, DFEAT, stats);

    // ---- molecular GCN branch ----
    deg_init<<<cdiv(N_MOL, 256), 256>>>(dinv, N_MOL);
    deg_count<<<cdiv(E_MOL_C, 256), 256>>>(dinv, mdst, E_MOL_C);
    deg_fin<<<cdiv(N_MOL, 256), 256>>>(dinv, N_MOL);

    // conv1: bufA = mol_x @ w1 ; bufB = bufA * dinv^2 (self loop, fused), then scatter into bufB
    gemm(mol_x, gcn_w1, bufA, N_MOL, GCN_H, GCN_IN, 0, 0, 1, bufB, dinv);
    {
        long etot = (long)E_MOL_C << 5;  // 128/4 = 32 float4
        gcn_scatter4<<<cdiv(etot, 256), 256>>>(bufB, bufA, msrc, mdst, dinv, E_MOL_C, 5);
    }
    run_bn(bufB, N_MOL, GCN_H, stats);

    // conv2: A=bufB -> C=bufA, C2=bufC (NO aliasing with A); scatter into bufC
    gemm(bufB, gcn_w2, bufA, N_MOL, DFEAT, GCN_H, 0, 0, 1, bufC, dinv);
    {
        long etot = (long)E_MOL_C << 6;  // 256/4 = 64 float4
        gcn_scatter4<<<cdiv(etot, 256), 256>>>(bufC, bufA, msrc, mdst, dinv, E_MOL_C, 6);
    }
    run_bn(bufC, N_MOL, DFEAT, stats);

    // ---- global mean pool (division fused into attention) ----
    zero_kernel<<<cdiv((long)N_DRUGS * DFEAT, 256), 256>>>(pool, (long)N_DRUGS * DFEAT);
    zero_kernel<<<cdiv(N_DRUGS, 256), 256>>>(pcnt, N_DRUGS);
    pool_add4<<<cdiv((long)N_MOL * 64, 256), 256>>>(pool, bufC, mol_batch, (long)N_MOL * 64);
    pool_cnt<<<cdiv(N_MOL, 256), 256>>>(pcnt, mol_batch, N_MOL);

    // ---- attention fusion -> xkg[0:N_DRUGS], beta -> out tail ----
    att_kernel<<<N_DRUGS, 128>>>(pool, pcnt, fpb, att_w1, att_b1, att_w2, xkg, out + N_KG * 2);
    copy_kernel<<<cdiv((long)N_GENE * DFEAT / 4, 256), 256>>>(
        (float4*)(xkg + (long)N_DRUGS * DFEAT), (const float4*)gene_emb, (long)N_GENE * DFEAT / 4);

    // ---- RGCN layer 1 (256 -> 256) ----
    gemm(xkg, rg_w1, hr, N_KG, DIM1, DFEAT, (long)DFEAT * DIM1, (long)N_KG * DIM1, R_REL);
    gemm(xkg, rg_root1, agg, N_KG, DIM1, DFEAT);
    zero_kernel<<<cdiv(R_REL * N_KG, 256), 256>>>(cnt, R_REL * N_KG);
    rgcn_cnt<<<cdiv(E_KG_C, 256), 256>>>(cnt, kg_et, kdst, E_KG_C);
    {
        long etot = (long)E_KG_C << 6;
        rgcn_scatter4<<<cdiv(etot, 256), 256>>>(agg, hr, ksrc, kdst, kg_et, cnt, E_KG_C, 6);
    }
    run_bn(agg, N_KG, DIM1, stats);

    // ---- RGCN layer 2 (256 -> 128) ----
    gemm(agg, rg_w2, hr, N_KG, DIM2, DIM1, (long)DIM1 * DIM2, (long)N_KG * DIM2, R_REL);
    gemm(agg, rg_root2, xkg, N_KG, DIM2, DIM1);
    {
        long etot = (long)E_KG_C << 5;
        rgcn_scatter4<<<cdiv(etot, 256), 256>>>(xkg, hr, ksrc, kdst, kg_et, cnt, E_KG_C, 5);
    }
    run_bn(xkg, N_KG, DIM2, stats);

    // ---- lin1 + bn + relu ----
    gemm(xkg, lin1_w, x3, N_KG, DIM3, DIM2);
    run_bn(x3, N_KG, DIM3, stats);

    // ---- lin2 + log_softmax ----
    lin2_k<<<cdiv(N_KG, 128), 128>>>(x3, lin2_w, lin2_b, out);
}

// round 4
// speedup vs baseline: 1.4822x; 1.1687x over previous
#include <cuda_runtime.h>
#include <cuda_bf16.h>
#include <math.h>

#define N_DRUGS 4096
#define N_GENE  5414
#define N_KG    9510
#define N_MOL   131072
#define E_MOL_C 524288
#define E_KG_C  524288
#define R_REL   8
#define MLP_IN  1024
#define MLP_H   512
#define DFEAT   256
#define GCN_IN  64
#define GCN_H   128
#define DIM1    256
#define DIM2    128
#define DIM3    64
#define EPSV    1e-5f

// ---------------- scratch ----------------
__device__ __align__(16) float g_h1[N_DRUGS * MLP_H];
__device__ __align__(16) float g_fp[N_DRUGS * DFEAT];
__device__ __align__(16) float g_bufA[(long)N_MOL * DFEAT];
__device__ __align__(16) float g_bufB[(long)N_MOL * DFEAT];
__device__ __align__(16) float g_bufC[(long)N_MOL * DFEAT];
__device__ __align__(16) float g_dinv[N_MOL];
__device__ __align__(16) float g_pool[N_DRUGS * DFEAT];
__device__ __align__(16) float g_pcnt[N_DRUGS];
__device__ __align__(16) float g_xkg[N_KG * DFEAT];
__device__ __align__(16) float g_hr[(long)R_REL * N_KG * DFEAT];   // also AGG [N_KG, 2048]
__device__ __align__(16) float g_agg[N_KG * DFEAT];
__device__ __align__(16) float g_cnt[R_REL * N_KG];
__device__ __align__(16) float g_x3[N_KG * DIM3];
__device__ __align__(16) float g_stats[4 * 512];

// ---------------- fp32x2 helpers ----------------
__device__ __forceinline__ unsigned long long ffma2(unsigned long long a, unsigned long long b,
                                                    unsigned long long c) {
    unsigned long long d;
    asm("fma.rn.f32x2 %0, %1, %2, %3;" : "=l"(d) : "l"(a), "l"(b), "l"(c));
    return d;
}
__device__ __forceinline__ unsigned long long bcast2(float x) {
    unsigned long long d;
    unsigned r = __float_as_uint(x);
    asm("mov.b64 %0, {%1, %1};" : "=l"(d) : "r"(r));
    return d;
}

// ---------------- utility kernels ----------------
__global__ void zero_kernel(float* p, long n) {
    long i = (long)blockIdx.x * blockDim.x + threadIdx.x;
    if (i < n) p[i] = 0.0f;
}
__global__ void zero4_kernel(float4* p, long n4) {
    long i = (long)blockIdx.x * blockDim.x + threadIdx.x;
    if (i < n4) p[i] = make_float4(0.f, 0.f, 0.f, 0.f);
}
__global__ void copy_kernel(float4* dst, const float4* src, long n4) {
    long i = (long)blockIdx.x * blockDim.x + threadIdx.x;
    if (i < n4) dst[i] = src[i];
}

// ---------------- SGEMM 128x128x16, double buffered, FFMA2 8x8 per thread ----------------
// C[M,N] (+)= A[M,K_chunk] @ B[K_chunk,N] per z-slice.
// A row stride = lda; per-z offsets: A += z*sA, B += z*sB, C += z*sC.
// accum: 0 = store, 2 = atomicAdd into C (split-K; C must be pre-initialized).
__global__ __launch_bounds__(256, 2)
void sgemm128(const float* __restrict__ A, const float* __restrict__ B,
              float* __restrict__ C, int M, int N, int K, int lda,
              long sA, long sB, long sC, int accum) {
    const int BM = 128, BN = 128, BK = 16;
    __shared__ float As[2][BK][BM + 4];
    __shared__ float Bs[2][BK][BN];
    const float* Ap = A + (long)blockIdx.z * sA;
    const float* Bp = B + (long)blockIdx.z * sB;
    float* Cp = C + (long)blockIdx.z * sC;
    int tid = threadIdx.x;
    int row0 = blockIdx.y * BM, col0 = blockIdx.x * BN;
    int aRow = tid >> 2;
    int aCol = (tid & 3) << 2;
    int bRow = tid >> 5;
    int bCol = (tid & 31) << 2;
    int tm = (tid >> 4) << 3;
    int tn = (tid & 15) << 3;
    unsigned long long acc2[8][4];
#pragma unroll
    for (int i = 0; i < 8; i++)
#pragma unroll
        for (int j = 0; j < 4; j++) acc2[i][j] = 0ull;
    float4 ra[2], rb[2];
    int nk = K / BK;

    {
#pragma unroll
        for (int i = 0; i < 2; i++) {
            int gr = row0 + aRow + i * 64;
            float4 v = make_float4(0.f, 0.f, 0.f, 0.f);
            if (gr < M) v = *(const float4*)(Ap + (long)gr * lda + aCol);
            As[0][aCol + 0][aRow + i * 64] = v.x;
            As[0][aCol + 1][aRow + i * 64] = v.y;
            As[0][aCol + 2][aRow + i * 64] = v.z;
            As[0][aCol + 3][aRow + i * 64] = v.w;
        }
#pragma unroll
        for (int i = 0; i < 2; i++) {
            int gk = bRow + i * 8;
            int gc = col0 + bCol;
            float4 v = make_float4(0.f, 0.f, 0.f, 0.f);
            if (gc < N) v = *(const float4*)(Bp + (long)gk * N + gc);
            *(float4*)&Bs[0][bRow + i * 8][bCol] = v;
        }
    }
    __syncthreads();
    int cur = 0;
    for (int t = 0; t < nk; t++) {
        if (t + 1 < nk) {
            int k0 = (t + 1) * BK;
#pragma unroll
            for (int i = 0; i < 2; i++) {
                int gr = row0 + aRow + i * 64;
                ra[i] = make_float4(0.f, 0.f, 0.f, 0.f);
                if (gr < M) ra[i] = *(const float4*)(Ap + (long)gr * lda + k0 + aCol);
            }
#pragma unroll
            for (int i = 0; i < 2; i++) {
                int gk = k0 + bRow + i * 8;
                int gc = col0 + bCol;
                rb[i] = make_float4(0.f, 0.f, 0.f, 0.f);
                if (gc < N) rb[i] = *(const float4*)(Bp + (long)gk * N + gc);
            }
        }
#pragma unroll
        for (int kk = 0; kk < BK; kk++) {
            union { float f[8]; float4 v[2]; unsigned long long u[4]; } av, bv;
            av.v[0] = *(float4*)&As[cur][kk][tm];
            av.v[1] = *(float4*)&As[cur][kk][tm + 4];
            bv.v[0] = *(float4*)&Bs[cur][kk][tn];
            bv.v[1] = *(float4*)&Bs[cur][kk][tn + 4];
#pragma unroll
            for (int i = 0; i < 8; i++) {
                unsigned long long a2 = bcast2(av.f[i]);
#pragma unroll
                for (int jp = 0; jp < 4; jp++)
                    acc2[i][jp] = ffma2(a2, bv.u[jp], acc2[i][jp]);
            }
        }
        if (t + 1 < nk) {
            int nb = cur ^ 1;
#pragma unroll
            for (int i = 0; i < 2; i++) {
                As[nb][aCol + 0][aRow + i * 64] = ra[i].x;
                As[nb][aCol + 1][aRow + i * 64] = ra[i].y;
                As[nb][aCol + 2][aRow + i * 64] = ra[i].z;
                As[nb][aCol + 3][aRow + i * 64] = ra[i].w;
            }
#pragma unroll
            for (int i = 0; i < 2; i++)
                *(float4*)&Bs[nb][bRow + i * 8][bCol] = rb[i];
            __syncthreads();
            cur = nb;
        }
    }
    bool fullN = (col0 + BN <= N);
#pragma unroll
    for (int i = 0; i < 8; i++) {
        int gr = row0 + tm + i;
        if (gr >= M) break;
        float* accf = (float*)acc2[i];
        float* crow = Cp + (long)gr * N;
        if (accum == 2) {
#pragma unroll
            for (int j = 0; j < 8; j++) {
                int gc = col0 + tn + j;
                if (gc < N) atomicAdd(&crow[gc], accf[j]);
            }
        } else if (fullN) {
            *(float4*)&crow[col0 + tn] = *(float4*)&accf[0];
            *(float4*)&crow[col0 + tn + 4] = *(float4*)&accf[4];
        } else {
#pragma unroll
            for (int j = 0; j < 8; j++) {
                int gc = col0 + tn + j;
                if (gc < N) crow[gc] = accf[j];
            }
        }
    }
}

// ---------------- BatchNorm ----------------
__global__ void bn_partial(const float* __restrict__ X, int M, int F,
                           float* __restrict__ colsum, float* __restrict__ colsq) {
    float s0 = 0.f, s1 = 0.f, q0 = 0.f, q1 = 0.f;
    int f0 = threadIdx.x, f1 = threadIdx.x + 256;
    for (int r = blockIdx.x; r < M; r += gridDim.x) {
        const float* row = X + (long)r * F;
        if (f0 < F) { float v = row[f0]; s0 += v; q0 += v * v; }
        if (f1 < F) { float v = row[f1]; s1 += v; q1 += v * v; }
    }
    if (f0 < F) { atomicAdd(&colsum[f0], s0); atomicAdd(&colsq[f0], q0); }
    if (f1 < F) { atomicAdd(&colsum[f1], s1); atomicAdd(&colsq[f1], q1); }
}

__global__ void bn_finalize(int M, int F, const float* __restrict__ colsum,
                            const float* __restrict__ colsq,
                            float* __restrict__ mean, float* __restrict__ rstd) {
    int f = blockIdx.x * blockDim.x + threadIdx.x;
    if (f < F) {
        float m = colsum[f] / (float)M;
        float v = colsq[f] / (float)M - m * m;
        mean[f] = m;
        rstd[f] = rsqrtf(fmaxf(v, 0.0f) + EPSV);
    }
}

__global__ void bn_apply_relu4(float4* __restrict__ X, long total4, int F4,
                               const float* __restrict__ mean, const float* __restrict__ rstd) {
    long i = (long)blockIdx.x * blockDim.x + threadIdx.x;
    if (i < total4) {
        int f4 = (int)(i % F4);
        int f = f4 * 4;
        float4 v = X[i];
        v.x = fmaxf((v.x - mean[f + 0]) * rstd[f + 0], 0.f);
        v.y = fmaxf((v.y - mean[f + 1]) * rstd[f + 1], 0.f);
        v.z = fmaxf((v.z - mean[f + 2]) * rstd[f + 2], 0.f);
        v.w = fmaxf((v.w - mean[f + 3]) * rstd[f + 3], 0.f);
        X[i] = v;
    }
}

// ---------------- GCN pieces (aggregate-first) ----------------
__global__ void deg_init(float* deg, int n) {
    int i = blockIdx.x * blockDim.x + threadIdx.x;
    if (i < n) deg[i] = 1.0f;
}
__global__ void deg_count(float* deg, const int* __restrict__ dst, int E) {
    int e = blockIdx.x * blockDim.x + threadIdx.x;
    if (e < E) atomicAdd(&deg[dst[e]], 1.0f);
}
__global__ void deg_fin(float* dinv, int n) {
    int i = blockIdx.x * blockDim.x + threadIdx.x;
    if (i < n) dinv[i] = rsqrtf(dinv[i]);
}
// out[i,:] = x[i,:] * dinv[i]^2  (self-loop term)
__global__ void gcn_selfinit4(float4* __restrict__ out, const float4* __restrict__ x,
                              const float* __restrict__ dinv, long total4, int logF4) {
    long idx = (long)blockIdx.x * blockDim.x + threadIdx.x;
    if (idx >= total4) return;
    int i = (int)(idx >> logF4);
    float di = dinv[i];
    float s = di * di;
    float4 v = x[idx];
    v.x *= s; v.y *= s; v.z *= s; v.w *= s;
    out[idx] = v;
}
__global__ void gcn_scatter4(float* __restrict__ out, const float* __restrict__ h,
                             const int* __restrict__ src, const int* __restrict__ dst,
                             const float* __restrict__ dinv, int E, int logF4) {
    long idx = (long)blockIdx.x * blockDim.x + threadIdx.x;
    long total = (long)E << logF4;
    if (idx >= total) return;
    int e = (int)(idx >> logF4);
    int f4 = (int)(idx & ((1 << logF4) - 1));
    int s = src[e], d = dst[e];
    float nrm = dinv[s] * dinv[d];
    float4 v = *(const float4*)(h + (((long)s << logF4) + f4) * 4);
    float* o = out + (((long)d << logF4) + f4) * 4;
    atomicAdd(o + 0, v.x * nrm);
    atomicAdd(o + 1, v.y * nrm);
    atomicAdd(o + 2, v.z * nrm);
    atomicAdd(o + 3, v.w * nrm);
}

// ---------------- pooling ----------------
__global__ void pool_add4(float* __restrict__ pool, const float* __restrict__ g,
                          const int* __restrict__ batch, long total4) {
    long idx = (long)blockIdx.x * blockDim.x + threadIdx.x;
    if (idx >= total4) return;
    int i = (int)(idx >> 6);
    int f4 = (int)(idx & 63);
    float4 v = *(const float4*)(g + ((long)i * DFEAT) + f4 * 4);
    float* p = pool + (long)batch[i] * DFEAT + f4 * 4;
    atomicAdd(p + 0, v.x);
    atomicAdd(p + 1, v.y);
    atomicAdd(p + 2, v.z);
    atomicAdd(p + 3, v.w);
}
__global__ void pool_cnt(float* __restrict__ cnt, const int* __restrict__ batch, int n) {
    int i = blockIdx.x * blockDim.x + threadIdx.x;
    if (i < n) atomicAdd(&cnt[batch[i]], 1.0f);
}

// ---------------- attention fusion ----------------
__global__ void att_kernel(const float* __restrict__ pool, const float* __restrict__ pcnt,
                           const float* __restrict__ fp,
                           const float* __restrict__ w1, const float* __restrict__ b1,
                           const float* __restrict__ w2, float* __restrict__ xkg,
                           float* __restrict__ beta_out) {
    int n = blockIdx.x;
    int tid = threadIdx.x;  // 128
    __shared__ float z0[256], z1[256];
    __shared__ float red0[4], red1[4];
    __shared__ float bsh[2];
    float invc = 1.0f / fmaxf(pcnt[n], 1.0f);
    for (int i = tid; i < 256; i += 128) {
        z0[i] = pool[(long)n * 256 + i] * invc;
        z1[i] = fp[(long)n * 256 + i];
    }
    __syncthreads();
    float s0 = 0.f, s1 = 0.f;
#pragma unroll 4
    for (int d = 0; d < 256; d++) {
        float w = w1[d * 128 + tid];
        s0 += z0[d] * w;
        s1 += z1[d] * w;
    }
    float bb = b1[tid], ww = w2[tid];
    float t0 = tanhf(s0 + bb) * ww;
    float t1 = tanhf(s1 + bb) * ww;
#pragma unroll
    for (int o = 16; o > 0; o >>= 1) {
        t0 += __shfl_down_sync(0xffffffffu, t0, o);
        t1 += __shfl_down_sync(0xffffffffu, t1, o);
    }
    int wid = tid >> 5, lid = tid & 31;
    if (lid == 0) { red0[wid] = t0; red1[wid] = t1; }
    __syncthreads();
    if (tid == 0) {
        float a0 = red0[0] + red0[1] + red0[2] + red0[3];
        float a1 = red1[0] + red1[1] + red1[2] + red1[3];
        float m = fmaxf(a0, a1);
        float e0 = expf(a0 - m), e1 = expf(a1 - m);
        float inv = 1.0f / (e0 + e1);
        bsh[0] = e0 * inv; bsh[1] = e1 * inv;
        beta_out[2 * n] = e0 * inv;
        beta_out[2 * n + 1] = e1 * inv;
    }
    __syncthreads();
    float b0v = bsh[0], b1v = bsh[1];
    for (int i = tid; i < 256; i += 128)
        xkg[(long)n * 256 + i] = b0v * z0[i] + b1v * z1[i];
}

// ---------------- RGCN pieces ----------------
__global__ void rgcn_cnt(float* __restrict__ cnt, const int* __restrict__ et,
                         const int* __restrict__ dst, int E) {
    int e = blockIdx.x * blockDim.x + threadIdx.x;
    if (e < E) atomicAdd(&cnt[et[e] * N_KG + dst[e]], 1.0f);
}
// Layer-1 aggregate-first: AGG[d, r*256 + f] += x[s, f] * (1/cnt[r,d])
__global__ void rgcn_scatter_pre(float* __restrict__ AGG, const float* __restrict__ x,
                                 const int* __restrict__ src, const int* __restrict__ dst,
                                 const int* __restrict__ et, const float* __restrict__ cnt,
                                 int E) {
    long idx = (long)blockIdx.x * blockDim.x + threadIdx.x;
    long total = (long)E << 6;  // 64 float4 per edge
    if (idx >= total) return;
    int e = (int)(idx >> 6);
    int f4 = (int)(idx & 63);
    int r = et[e], s = src[e], d = dst[e];
    float nrm = 1.0f / fmaxf(cnt[r * N_KG + d], 1.0f);
    float4 v = *(const float4*)(x + (long)s * 256 + f4 * 4);
    float* o = AGG + (long)d * 2048 + r * 256 + f4 * 4;
    atomicAdd(o + 0, v.x * nrm);
    atomicAdd(o + 1, v.y * nrm);
    atomicAdd(o + 2, v.z * nrm);
    atomicAdd(o + 3, v.w * nrm);
}
// Layer-2 transform-first (hr layout [r][node][F])
__global__ void rgcn_scatter4(float* __restrict__ agg, const float* __restrict__ hr,
                              const int* __restrict__ src, const int* __restrict__ dst,
                              const int* __restrict__ et, const float* __restrict__ cnt,
                              int E, int logF4) {
    long idx = (long)blockIdx.x * blockDim.x + threadIdx.x;
    long total = (long)E << logF4;
    if (idx >= total) return;
    int e = (int)(idx >> logF4);
    int f4 = (int)(idx & ((1 << logF4) - 1));
    int r = et[e];
    int s = src[e], d = dst[e];
    float nrm = 1.0f / fmaxf(cnt[r * N_KG + d], 1.0f);
    float4 v = *(const float4*)(hr + ((((long)r * N_KG + s) << logF4) + f4) * 4);
    float* o = agg + (((long)d << logF4) + f4) * 4;
    atomicAdd(o + 0, v.x * nrm);
    atomicAdd(o + 1, v.y * nrm);
    atomicAdd(o + 2, v.z * nrm);
    atomicAdd(o + 3, v.w * nrm);
}

// ---------------- final head ----------------
__global__ void lin2_k(const float* __restrict__ x, const float* __restrict__ w,
                       const float* __restrict__ b, float* __restrict__ out) {
    int row = blockIdx.x * blockDim.x + threadIdx.x;
    if (row >= N_KG) return;
    float l0 = b[0], l1 = b[1];
    const float* xr = x + (long)row * 64;
#pragma unroll
    for (int d = 0; d < 64; d++) {
        float v = xr[d];
        l0 += v * w[2 * d];
        l1 += v * w[2 * d + 1];
    }
    float m = fmaxf(l0, l1);
    float lse = m + logf(expf(l0 - m) + expf(l1 - m));
    out[2 * row] = l0 - lse;
    out[2 * row + 1] = l1 - lse;
}

// ---------------- host driver ----------------
static inline int cdiv(long a, long b) { return (int)((a + b - 1) / b); }

static void run_bn(float* X, int M, int F, float* stats) {
    float* colsum = stats;
    float* colsq = stats + 512;
    float* mean = stats + 1024;
    float* rstd = stats + 1536;
    zero_kernel<<<4, 256>>>(stats, 1024);
    int grid = M < 1184 ? M : 1184;
    bn_partial<<<grid, 256>>>(X, M, F, colsum, colsq);
    bn_finalize<<<cdiv(F, 128), 128>>>(M, F, colsum, colsq, mean, rstd);
    long total4 = (long)M * F / 4;
    bn_apply_relu4<<<cdiv(total4, 256), 256>>>((float4*)X, total4, F / 4, mean, rstd);
}

static void gemm(const float* A, const float* B, float* C, int M, int N, int K, int lda,
                 long sA = 0, long sB = 0, long sC = 0, int z = 1, int accum = 0) {
    dim3 grid(cdiv(N, 128), cdiv(M, 128), z);
    sgemm128<<<grid, 256>>>(A, B, C, M, N, K, lda, sA, sB, sC, accum);
}

extern "C" void kernel_launch(void* const* d_in, const int* in_sizes, int n_in,
                              void* d_out, int out_size) {
    const float* fp_data = (const float*)d_in[0];
    const float* mol_x   = (const float*)d_in[1];
    const int*   mol_batch = (const int*)d_in[2];
    const int*   mol_ei  = (const int*)d_in[3];
    const int*   kg_ei   = (const int*)d_in[4];
    const int*   kg_et   = (const int*)d_in[5];
    const float* fp_w1   = (const float*)d_in[6];
    const float* fp_w2   = (const float*)d_in[8];
    const float* gcn_w1  = (const float*)d_in[10];
    const float* gcn_w2  = (const float*)d_in[12];
    const float* att_w1  = (const float*)d_in[14];
    const float* att_b1  = (const float*)d_in[15];
    const float* att_w2  = (const float*)d_in[16];
    const float* gene_emb = (const float*)d_in[17];
    const float* rg_w1   = (const float*)d_in[18];
    const float* rg_root1 = (const float*)d_in[19];
    const float* rg_w2   = (const float*)d_in[21];
    const float* rg_root2 = (const float*)d_in[22];
    const float* lin1_w  = (const float*)d_in[24];
    const float* lin2_w  = (const float*)d_in[26];
    const float* lin2_b  = (const float*)d_in[27];
    float* out = (float*)d_out;

    float *h1, *fpb, *bufA, *bufB, *bufC, *dinv, *pool, *pcnt, *xkg, *hr, *agg, *cnt, *x3, *stats;
    cudaGetSymbolAddress((void**)&h1, g_h1);
    cudaGetSymbolAddress((void**)&fpb, g_fp);
    cudaGetSymbolAddress((void**)&bufA, g_bufA);
    cudaGetSymbolAddress((void**)&bufB, g_bufB);
    cudaGetSymbolAddress((void**)&bufC, g_bufC);
    cudaGetSymbolAddress((void**)&dinv, g_dinv);
    cudaGetSymbolAddress((void**)&pool, g_pool);
    cudaGetSymbolAddress((void**)&pcnt, g_pcnt);
    cudaGetSymbolAddress((void**)&xkg, g_xkg);
    cudaGetSymbolAddress((void**)&hr, g_hr);
    cudaGetSymbolAddress((void**)&agg, g_agg);
    cudaGetSymbolAddress((void**)&cnt, g_cnt);
    cudaGetSymbolAddress((void**)&x3, g_x3);
    cudaGetSymbolAddress((void**)&stats, g_stats);

    const int* msrc = mol_ei;
    const int* mdst = mol_ei + E_MOL_C;
    const int* ksrc = kg_ei;
    const int* kdst = kg_ei + E_KG_C;

    // ---- fingerprint MLP branch (biases cancel under BN); split-K z=4 ----
    zero4_kernel<<<cdiv((long)N_DRUGS * MLP_H / 4, 256), 256>>>((float4*)h1, (long)N_DRUGS * MLP_H / 4);
    gemm(fp_data, fp_w1, h1, N_DRUGS, MLP_H, MLP_IN / 4, MLP_IN,
         MLP_IN / 4, (long)(MLP_IN / 4) * MLP_H, 0, 4, 2);
    run_bn(h1, N_DRUGS, MLP_H, stats);
    zero4_kernel<<<cdiv((long)N_DRUGS * DFEAT / 4, 256), 256>>>((float4*)fpb, (long)N_DRUGS * DFEAT / 4);
    gemm(h1, fp_w2, fpb, N_DRUGS, DFEAT, MLP_H / 4, MLP_H,
         MLP_H / 4, (long)(MLP_H / 4) * DFEAT, 0, 4, 2);
    run_bn(fpb, N_DRUGS, DFEAT, stats);

    // ---- molecular GCN branch (aggregate-then-transform) ----
    deg_init<<<cdiv(N_MOL, 256), 256>>>(dinv, N_MOL);
    deg_count<<<cdiv(E_MOL_C, 256), 256>>>(dinv, mdst, E_MOL_C);
    deg_fin<<<cdiv(N_MOL, 256), 256>>>(dinv, N_MOL);

    // conv1: aggX (bufA) = A_norm @ mol_x [N_MOL,64]; then GEMM @ w1 -> bufB [N_MOL,128]
    {
        long t4 = (long)N_MOL * (GCN_IN / 4);
        gcn_selfinit4<<<cdiv(t4, 256), 256>>>((float4*)bufA, (const float4*)mol_x, dinv, t4, 4);
        long etot = (long)E_MOL_C << 4;
        gcn_scatter4<<<cdiv(etot, 256), 256>>>(bufA, mol_x, msrc, mdst, dinv, E_MOL_C, 4);
    }
    gemm(bufA, gcn_w1, bufB, N_MOL, GCN_H, GCN_IN, GCN_IN);
    run_bn(bufB, N_MOL, GCN_H, stats);

    // conv2: aggG (bufC) = A_norm @ bufB [N_MOL,128]; GEMM @ w2 -> bufA [N_MOL,256]
    {
        long t4 = (long)N_MOL * (GCN_H / 4);
        gcn_selfinit4<<<cdiv(t4, 256), 256>>>((float4*)bufC, (const float4*)bufB, dinv, t4, 5);
        long etot = (long)E_MOL_C << 5;
        gcn_scatter4<<<cdiv(etot, 256), 256>>>(bufC, bufB, msrc, mdst, dinv, E_MOL_C, 5);
    }
    gemm(bufC, gcn_w2, bufA, N_MOL, DFEAT, GCN_H, GCN_H);
    run_bn(bufA, N_MOL, DFEAT, stats);

    // ---- global mean pool (division fused into attention) ----
    zero4_kernel<<<cdiv((long)N_DRUGS * DFEAT / 4, 256), 256>>>((float4*)pool, (long)N_DRUGS * DFEAT / 4);
    zero_kernel<<<cdiv(N_DRUGS, 256), 256>>>(pcnt, N_DRUGS);
    pool_add4<<<cdiv((long)N_MOL * 64, 256), 256>>>(pool, bufA, mol_batch, (long)N_MOL * 64);
    pool_cnt<<<cdiv(N_MOL, 256), 256>>>(pcnt, mol_batch, N_MOL);

    // ---- attention fusion -> xkg[0:N_DRUGS], beta -> out tail ----
    att_kernel<<<N_DRUGS, 128>>>(pool, pcnt, fpb, att_w1, att_b1, att_w2, xkg, out + N_KG * 2);
    copy_kernel<<<cdiv((long)N_GENE * DFEAT / 4, 256), 256>>>(
        (float4*)(xkg + (long)N_DRUGS * DFEAT), (const float4*)gene_emb, (long)N_GENE * DFEAT / 4);

    // ---- relation counts (shared by both RGCN layers) ----
    zero_kernel<<<cdiv(R_REL * N_KG, 256), 256>>>(cnt, R_REL * N_KG);
    rgcn_cnt<<<cdiv(E_KG_C, 256), 256>>>(cnt, kg_et, kdst, E_KG_C);

    // ---- RGCN layer 1: aggregate-first into AGG [N_KG, 2048], flat GEMM + split-K ----
    {
        long n4 = (long)N_KG * 2048 / 4;
        zero4_kernel<<<cdiv(n4, 256), 256>>>((float4*)hr, n4);
        long etot = (long)E_KG_C << 6;
        rgcn_scatter_pre<<<cdiv(etot, 256), 256>>>(hr, xkg, ksrc, kdst, kg_et, cnt, E_KG_C);
    }
    gemm(xkg, rg_root1, agg, N_KG, DIM1, DFEAT, DFEAT);   // agg = x @ root1
    gemm(hr, rg_w1, agg, N_KG, DIM1, 256, 2048,
         256, (long)256 * DIM1, 0, 8, 2);                 // agg += AGG @ Wstack1 (split-K z=8)
    run_bn(agg, N_KG, DIM1, stats);

    // ---- RGCN layer 2: transform-first (batched), scatter into xkg ----
    gemm(agg, rg_w2, hr, N_KG, DIM2, DIM1, DIM1,
         0, (long)DIM1 * DIM2, (long)N_KG * DIM2, R_REL, 0);
    gemm(agg, rg_root2, xkg, N_KG, DIM2, DIM1, DIM1);
    {
        long etot = (long)E_KG_C << 5;
        rgcn_scatter4<<<cdiv(etot, 256), 256>>>(xkg, hr, ksrc, kdst, kg_et, cnt, E_KG_C, 5);
    }
    run_bn(xkg, N_KG, DIM2, stats);

    // ---- lin1 + bn + relu ----
    gemm(xkg, lin1_w, x3, N_KG, DIM3, DIM2, DIM2);
    run_bn(x3, N_KG, DIM3, stats);

    // ---- lin2 + log_softmax ----
    lin2_k<<<cdiv(N_KG, 128), 128>>>(x3, lin2_w, lin2_b, out);
}

// round 5
// speedup vs baseline: 1.8720x; 1.2630x over previous
#include <cuda_runtime.h>
#include <cuda_bf16.h>
#include <math.h>

#define N_DRUGS 4096
#define N_GENE  5414
#define N_KG    9510
#define N_MOL   131072
#define E_MOL_C 524288
#define E_KG_C  524288
#define R_REL   8
#define MLP_IN  1024
#define MLP_H   512
#define DFEAT   256
#define GCN_IN  64
#define GCN_H   128
#define DIM1    256
#define DIM2    128
#define DIM3    64
#define EPSV    1e-5f
#define NKEY_KG (N_KG * R_REL)

// ---------------- scratch ----------------
__device__ __align__(16) float g_h1[N_DRUGS * MLP_H];
__device__ __align__(16) float g_fp[N_DRUGS * DFEAT];
__device__ __align__(16) float g_bufA[(long)N_MOL * DFEAT];
__device__ __align__(16) float g_bufB[(long)N_MOL * DFEAT];
__device__ __align__(16) float g_bufC[(long)N_MOL * DFEAT];
__device__ __align__(16) float g_dinv[N_MOL];
__device__ __align__(16) float g_pool[N_DRUGS * DFEAT];
__device__ __align__(16) float g_xkg[N_KG * DFEAT];
__device__ __align__(16) float g_hr[(long)R_REL * N_KG * DFEAT];   // also AGG [N_KG, 2048]
__device__ __align__(16) float g_agg[N_KG * DFEAT];
__device__ __align__(16) float g_x3[N_KG * DIM3];
__device__ __align__(16) float g_stats[4 * 512];
// CSR scratch
__device__ int g_hist_mol[N_MOL];
__device__ int g_base_mol[N_MOL + 1];
__device__ int g_off_mol[N_MOL];
__device__ int g_ssrc_mol[E_MOL_C];
__device__ int g_hist_kg[NKEY_KG];
__device__ int g_base_kg[NKEY_KG + 1];
__device__ int g_off_kg[NKEY_KG];
__device__ int g_ssrc_kg[E_KG_C];

// ---------------- fp32x2 / red helpers ----------------
__device__ __forceinline__ unsigned long long ffma2(unsigned long long a, unsigned long long b,
                                                    unsigned long long c) {
    unsigned long long d;
    asm("fma.rn.f32x2 %0, %1, %2, %3;" : "=l"(d) : "l"(a), "l"(b), "l"(c));
    return d;
}
__device__ __forceinline__ unsigned long long bcast2(float x) {
    unsigned long long d;
    unsigned r = __float_as_uint(x);
    asm("mov.b64 %0, {%1, %1};" : "=l"(d) : "r"(r));
    return d;
}
__device__ __forceinline__ void red4(float* addr, float4 v) {
    asm volatile("red.global.add.v4.f32 [%0], {%1, %2, %3, %4};"
                 :: "l"(addr), "f"(v.x), "f"(v.y), "f"(v.z), "f"(v.w) : "memory");
}

// ---------------- utility kernels ----------------
__global__ void zero4_kernel(float4* p, long n4) {
    long i = (long)blockIdx.x * blockDim.x + threadIdx.x;
    if (i < n4) p[i] = make_float4(0.f, 0.f, 0.f, 0.f);
}
__global__ void zero_kernel(float* p, long n) {
    long i = (long)blockIdx.x * blockDim.x + threadIdx.x;
    if (i < n) p[i] = 0.0f;
}
__global__ void zero_int(int* p, int n) {
    int i = blockIdx.x * blockDim.x + threadIdx.x;
    if (i < n) p[i] = 0;
}
__global__ void copy_kernel(float4* dst, const float4* src, long n4) {
    long i = (long)blockIdx.x * blockDim.x + threadIdx.x;
    if (i < n4) dst[i] = src[i];
}

// ---------------- CSR build ----------------
__global__ void hist_mol_k(int* hist, const int* __restrict__ dst, int E) {
    int e = blockIdx.x * blockDim.x + threadIdx.x;
    if (e < E) atomicAdd(&hist[dst[e]], 1);
}
__global__ void hist_kg_k(int* hist, const int* __restrict__ dst, const int* __restrict__ et, int E) {
    int e = blockIdx.x * blockDim.x + threadIdx.x;
    if (e < E) atomicAdd(&hist[dst[e] * R_REL + et[e]], 1);
}
// single-block exclusive scan (n up to ~131K), 1024 threads, 4 elems/thread/chunk
__global__ void scan_excl(const int* __restrict__ hist, int* __restrict__ base,
                          int* __restrict__ off, int n) {
    __shared__ int wsum[32];
    __shared__ int carry;
    int t = threadIdx.x, lane = t & 31, wid = t >> 5;
    if (t == 0) carry = 0;
    __syncthreads();
    for (int c0 = 0; c0 < n; c0 += 4096) {
        int i0 = c0 + t * 4;
        int v0 = (i0 < n) ? hist[i0] : 0;
        int v1 = (i0 + 1 < n) ? hist[i0 + 1] : 0;
        int v2 = (i0 + 2 < n) ? hist[i0 + 2] : 0;
        int v3 = (i0 + 3 < n) ? hist[i0 + 3] : 0;
        int s = v0 + v1 + v2 + v3;
        int sc = s;
#pragma unroll
        for (int o = 1; o < 32; o <<= 1) {
            int u = __shfl_up_sync(0xffffffffu, sc, o);
            if (lane >= o) sc += u;
        }
        if (lane == 31) wsum[wid] = sc;
        __syncthreads();
        if (wid == 0) {
            int w = wsum[lane];
            int wc = w;
#pragma unroll
            for (int o = 1; o < 32; o <<= 1) {
                int u = __shfl_up_sync(0xffffffffu, wc, o);
                if (lane >= o) wc += u;
            }
            wsum[lane] = wc - w;  // exclusive warp offsets
        }
        __syncthreads();
        int excl = carry + wsum[wid] + (sc - s);
        if (i0 < n) { base[i0] = excl; off[i0] = excl; }
        excl += v0;
        if (i0 + 1 < n) { base[i0 + 1] = excl; off[i0 + 1] = excl; }
        excl += v1;
        if (i0 + 2 < n) { base[i0 + 2] = excl; off[i0 + 2] = excl; }
        excl += v2;
        if (i0 + 3 < n) { base[i0 + 3] = excl; off[i0 + 3] = excl; }
        __syncthreads();
        if (t == 1023) carry += wsum[31] + sc;
        __syncthreads();
    }
    if (t == 0) base[n] = carry;
}
__global__ void reorder_mol(const int* __restrict__ src, const int* __restrict__ dst,
                            int* off, int* ssrc, int E) {
    int e = blockIdx.x * blockDim.x + threadIdx.x;
    if (e < E) {
        int p = atomicAdd(&off[dst[e]], 1);
        ssrc[p] = src[e];
    }
}
__global__ void reorder_kg(const int* __restrict__ src, const int* __restrict__ dst,
                           const int* __restrict__ et, int* off, int* ssrc, int E) {
    int e = blockIdx.x * blockDim.x + threadIdx.x;
    if (e < E) {
        int p = atomicAdd(&off[dst[e] * R_REL + et[e]], 1);
        ssrc[p] = src[e];
    }
}
__global__ void dinv_k(float* dinv, const int* __restrict__ hist, int n) {
    int i = blockIdx.x * blockDim.x + threadIdx.x;
    if (i < n) dinv[i] = rsqrtf((float)hist[i] + 1.0f);  // +1 self loop
}

// ---------------- GCN aggregation (no atomics): block per dst, F threads ----------------
__global__ void gcn_agg(const float* __restrict__ x, const int* __restrict__ ssrc,
                        const int* __restrict__ base, const float* __restrict__ dinv,
                        float* __restrict__ out, int F) {
    int d = blockIdx.x;
    int t = threadIdx.x;
    int s0 = base[d], s1 = base[d + 1];
    float a0 = 0.f, a1 = 0.f;
    int p = s0;
    for (; p + 1 < s1; p += 2) {
        int sA = ssrc[p], sB = ssrc[p + 1];
        a0 += dinv[sA] * x[(long)sA * F + t];
        a1 += dinv[sB] * x[(long)sB * F + t];
    }
    if (p < s1) {
        int sA = ssrc[p];
        a0 += dinv[sA] * x[(long)sA * F + t];
    }
    float dd = dinv[d];
    out[(long)d * F + t] = dd * (a0 + a1) + dd * dd * x[(long)d * F + t];
}

// ---------------- RGCN aggregation (no atomics) ----------------
// layer 1: AGG[d, r*256 + t] = mean over group (d,r) of x[src, t]
__global__ void rgcn_agg1(const float* __restrict__ x, const int* __restrict__ ssrc,
                          const int* __restrict__ base, float* __restrict__ AGG) {
    int d = blockIdx.x;
    int t = threadIdx.x;  // 256
#pragma unroll
    for (int r = 0; r < R_REL; r++) {
        int k = d * R_REL + r;
        int s0 = base[k], s1 = base[k + 1];
        float a0 = 0.f, a1 = 0.f;
        int p = s0;
        for (; p + 1 < s1; p += 2) {
            a0 += x[(long)ssrc[p] * 256 + t];
            a1 += x[(long)ssrc[p + 1] * 256 + t];
        }
        if (p < s1) a0 += x[(long)ssrc[p] * 256 + t];
        float nrm = (s1 > s0) ? 1.0f / (float)(s1 - s0) : 0.0f;
        AGG[(long)d * 2048 + r * 256 + t] = (a0 + a1) * nrm;
    }
}
// layer 2: xkg[d, t] += sum_r mean over group (d,r) of hr[r, src, t]
__global__ void rgcn_agg2(const float* __restrict__ hr, const int* __restrict__ ssrc,
                          const int* __restrict__ base, float* __restrict__ xkg) {
    int d = blockIdx.x;
    int t = threadIdx.x;  // 128
    float tot = 0.f;
#pragma unroll
    for (int r = 0; r < R_REL; r++) {
        int k = d * R_REL + r;
        int s0 = base[k], s1 = base[k + 1];
        float a0 = 0.f, a1 = 0.f;
        int p = s0;
        const float* hp = hr + (long)r * N_KG * 128;
        for (; p + 1 < s1; p += 2) {
            a0 += hp[(long)ssrc[p] * 128 + t];
            a1 += hp[(long)ssrc[p + 1] * 128 + t];
        }
        if (p < s1) a0 += hp[(long)ssrc[p] * 128 + t];
        if (s1 > s0) tot += (a0 + a1) / (float)(s1 - s0);
    }
    xkg[(long)d * 128 + t] += tot;
}

// ---------------- SGEMM 128x128x16, double buffered, FFMA2 8x8 per thread ----------------
__global__ __launch_bounds__(256, 2)
void sgemm128(const float* __restrict__ A, const float* __restrict__ B,
              float* __restrict__ C, int M, int N, int K, int lda,
              long sA, long sB, long sC, int accum) {
    const int BM = 128, BN = 128, BK = 16;
    __shared__ float As[2][BK][BM + 4];
    __shared__ float Bs[2][BK][BN];
    const float* Ap = A + (long)blockIdx.z * sA;
    const float* Bp = B + (long)blockIdx.z * sB;
    float* Cp = C + (long)blockIdx.z * sC;
    int tid = threadIdx.x;
    int row0 = blockIdx.y * BM, col0 = blockIdx.x * BN;
    int aRow = tid >> 2;
    int aCol = (tid & 3) << 2;
    int bRow = tid >> 5;
    int bCol = (tid & 31) << 2;
    int tm = (tid >> 4) << 3;
    int tn = (tid & 15) << 3;
    unsigned long long acc2[8][4];
#pragma unroll
    for (int i = 0; i < 8; i++)
#pragma unroll
        for (int j = 0; j < 4; j++) acc2[i][j] = 0ull;
    float4 ra[2], rb[2];
    int nk = K / BK;

    {
#pragma unroll
        for (int i = 0; i < 2; i++) {
            int gr = row0 + aRow + i * 64;
            float4 v = make_float4(0.f, 0.f, 0.f, 0.f);
            if (gr < M) v = *(const float4*)(Ap + (long)gr * lda + aCol);
            As[0][aCol + 0][aRow + i * 64] = v.x;
            As[0][aCol + 1][aRow + i * 64] = v.y;
            As[0][aCol + 2][aRow + i * 64] = v.z;
            As[0][aCol + 3][aRow + i * 64] = v.w;
        }
#pragma unroll
        for (int i = 0; i < 2; i++) {
            int gk = bRow + i * 8;
            int gc = col0 + bCol;
            float4 v = make_float4(0.f, 0.f, 0.f, 0.f);
            if (gc < N) v = *(const float4*)(Bp + (long)gk * N + gc);
            *(float4*)&Bs[0][bRow + i * 8][bCol] = v;
        }
    }
    __syncthreads();
    int cur = 0;
    for (int t = 0; t < nk; t++) {
        if (t + 1 < nk) {
            int k0 = (t + 1) * BK;
#pragma unroll
            for (int i = 0; i < 2; i++) {
                int gr = row0 + aRow + i * 64;
                ra[i] = make_float4(0.f, 0.f, 0.f, 0.f);
                if (gr < M) ra[i] = *(const float4*)(Ap + (long)gr * lda + k0 + aCol);
            }
#pragma unroll
            for (int i = 0; i < 2; i++) {
                int gk = k0 + bRow + i * 8;
                int gc = col0 + bCol;
                rb[i] = make_float4(0.f, 0.f, 0.f, 0.f);
                if (gc < N) rb[i] = *(const float4*)(Bp + (long)gk * N + gc);
            }
        }
#pragma unroll
        for (int kk = 0; kk < BK; kk++) {
            union { float f[8]; float4 v[2]; unsigned long long u[4]; } av, bv;
            av.v[0] = *(float4*)&As[cur][kk][tm];
            av.v[1] = *(float4*)&As[cur][kk][tm + 4];
            bv.v[0] = *(float4*)&Bs[cur][kk][tn];
            bv.v[1] = *(float4*)&Bs[cur][kk][tn + 4];
#pragma unroll
            for (int i = 0; i < 8; i++) {
                unsigned long long a2 = bcast2(av.f[i]);
#pragma unroll
                for (int jp = 0; jp < 4; jp++)
                    acc2[i][jp] = ffma2(a2, bv.u[jp], acc2[i][jp]);
            }
        }
        if (t + 1 < nk) {
            int nb = cur ^ 1;
#pragma unroll
            for (int i = 0; i < 2; i++) {
                As[nb][aCol + 0][aRow + i * 64] = ra[i].x;
                As[nb][aCol + 1][aRow + i * 64] = ra[i].y;
                As[nb][aCol + 2][aRow + i * 64] = ra[i].z;
                As[nb][aCol + 3][aRow + i * 64] = ra[i].w;
            }
#pragma unroll
            for (int i = 0; i < 2; i++)
                *(float4*)&Bs[nb][bRow + i * 8][bCol] = rb[i];
            __syncthreads();
            cur = nb;
        }
    }
    bool fullN = (col0 + BN <= N);
#pragma unroll
    for (int i = 0; i < 8; i++) {
        int gr = row0 + tm + i;
        if (gr >= M) break;
        float* accf = (float*)acc2[i];
        float* crow = Cp + (long)gr * N;
        if (accum == 2) {
            if (fullN) {
                red4(&crow[col0 + tn], *(float4*)&accf[0]);
                red4(&crow[col0 + tn + 4], *(float4*)&accf[4]);
            } else {
#pragma unroll
                for (int j = 0; j < 8; j++) {
                    int gc = col0 + tn + j;
                    if (gc < N) atomicAdd(&crow[gc], accf[j]);
                }
            }
        } else if (fullN) {
            *(float4*)&crow[col0 + tn] = *(float4*)&accf[0];
            *(float4*)&crow[col0 + tn + 4] = *(float4*)&accf[4];
        } else {
#pragma unroll
            for (int j = 0; j < 8; j++) {
                int gc = col0 + tn + j;
                if (gc < N) crow[gc] = accf[j];
            }
        }
    }
}

// ---------------- BatchNorm ----------------
__global__ void bn_partial(const float* __restrict__ X, int M, int F,
                           float* __restrict__ colsum, float* __restrict__ colsq) {
    float s0 = 0.f, s1 = 0.f, q0 = 0.f, q1 = 0.f;
    int f0 = threadIdx.x, f1 = threadIdx.x + 256;
    for (int r = blockIdx.x; r < M; r += gridDim.x) {
        const float* row = X + (long)r * F;
        if (f0 < F) { float v = row[f0]; s0 += v; q0 += v * v; }
        if (f1 < F) { float v = row[f1]; s1 += v; q1 += v * v; }
    }
    if (f0 < F) { atomicAdd(&colsum[f0], s0); atomicAdd(&colsq[f0], q0); }
    if (f1 < F) { atomicAdd(&colsum[f1], s1); atomicAdd(&colsq[f1], q1); }
}

__global__ void bn_finalize(int M, int F, const float* __restrict__ colsum,
                            const float* __restrict__ colsq,
                            float* __restrict__ mean, float* __restrict__ rstd) {
    int f = blockIdx.x * blockDim.x + threadIdx.x;
    if (f < F) {
        float m = colsum[f] / (float)M;
        float v = colsq[f] / (float)M - m * m;
        mean[f] = m;
        rstd[f] = rsqrtf(fmaxf(v, 0.0f) + EPSV);
    }
}

__global__ void bn_apply_relu4(float4* __restrict__ X, long total4, int F4,
                               const float* __restrict__ mean, const float* __restrict__ rstd) {
    long i = (long)blockIdx.x * blockDim.x + threadIdx.x;
    if (i < total4) {
        int f4 = (int)(i % F4);
        int f = f4 * 4;
        float4 v = X[i];
        v.x = fmaxf((v.x - mean[f + 0]) * rstd[f + 0], 0.f);
        v.y = fmaxf((v.y - mean[f + 1]) * rstd[f + 1], 0.f);
        v.z = fmaxf((v.z - mean[f + 2]) * rstd[f + 2], 0.f);
        v.w = fmaxf((v.w - mean[f + 3]) * rstd[f + 3], 0.f);
        X[i] = v;
    }
}

// BN(apply)+relu+mean-pool fused: block per drug (mol_batch sorted)
__global__ void bn_pool(const float* __restrict__ X, const int* __restrict__ batch,
                        const float* __restrict__ mean, const float* __restrict__ rstd,
                        float* __restrict__ pool) {
    int g = blockIdx.x;
    int t = threadIdx.x;  // 256
    __shared__ int sh_lo, sh_hi;
    if (t == 0) {
        int lo = 0, hi = N_MOL;
        while (lo < hi) { int m = (lo + hi) >> 1; if (batch[m] < g) lo = m + 1; else hi = m; }
        sh_lo = lo;
        int lo2 = lo, hi2 = N_MOL;
        while (lo2 < hi2) { int m = (lo2 + hi2) >> 1; if (batch[m] <= g) lo2 = m + 1; else hi2 = m; }
        sh_hi = lo2;
    }
    __syncthreads();
    int lo = sh_lo, hi = sh_hi;
    float m = mean[t], rs = rstd[t];
    float acc = 0.f;
    for (int i = lo; i < hi; i++) {
        float v = (X[(long)i * 256 + t] - m) * rs;
        acc += fmaxf(v, 0.f);
    }
    float c = (float)(hi - lo);
    pool[(long)g * 256 + t] = acc / fmaxf(c, 1.0f);
}

// ---------------- attention fusion ----------------
__global__ void att_kernel(const float* __restrict__ pool,
                           const float* __restrict__ fp,
                           const float* __restrict__ w1, const float* __restrict__ b1,
                           const float* __restrict__ w2, float* __restrict__ xkg,
                           float* __restrict__ beta_out) {
    int n = blockIdx.x;
    int tid = threadIdx.x;  // 128
    __shared__ float z0[256], z1[256];
    __shared__ float red0[4], red1[4];
    __shared__ float bsh[2];
    for (int i = tid; i < 256; i += 128) {
        z0[i] = pool[(long)n * 256 + i];
        z1[i] = fp[(long)n * 256 + i];
    }
    __syncthreads();
    float s0 = 0.f, s1 = 0.f;
#pragma unroll 4
    for (int d = 0; d < 256; d++) {
        float w = w1[d * 128 + tid];
        s0 += z0[d] * w;
        s1 += z1[d] * w;
    }
    float bb = b1[tid], ww = w2[tid];
    float t0 = tanhf(s0 + bb) * ww;
    float t1 = tanhf(s1 + bb) * ww;
#pragma unroll
    for (int o = 16; o > 0; o >>= 1) {
        t0 += __shfl_down_sync(0xffffffffu, t0, o);
        t1 += __shfl_down_sync(0xffffffffu, t1, o);
    }
    int wid = tid >> 5, lid = tid & 31;
    if (lid == 0) { red0[wid] = t0; red1[wid] = t1; }
    __syncthreads();
    if (tid == 0) {
        float a0 = red0[0] + red0[1] + red0[2] + red0[3];
        float a1 = red1[0] + red1[1] + red1[2] + red1[3];
        float m = fmaxf(a0, a1);
        float e0 = expf(a0 - m), e1 = expf(a1 - m);
        float inv = 1.0f / (e0 + e1);
        bsh[0] = e0 * inv; bsh[1] = e1 * inv;
        beta_out[2 * n] = e0 * inv;
        beta_out[2 * n + 1] = e1 * inv;
    }
    __syncthreads();
    float b0v = bsh[0], b1v = bsh[1];
    for (int i = tid; i < 256; i += 128)
        xkg[(long)n * 256 + i] = b0v * z0[i] + b1v * z1[i];
}

// ---------------- final head ----------------
__global__ void lin2_k(const float* __restrict__ x, const float* __restrict__ w,
                       const float* __restrict__ b, float* __restrict__ out) {
    int row = blockIdx.x * blockDim.x + threadIdx.x;
    if (row >= N_KG) return;
    float l0 = b[0], l1 = b[1];
    const float* xr = x + (long)row * 64;
#pragma unroll
    for (int d = 0; d < 64; d++) {
        float v = xr[d];
        l0 += v * w[2 * d];
        l1 += v * w[2 * d + 1];
    }
    float m = fmaxf(l0, l1);
    float lse = m + logf(expf(l0 - m) + expf(l1 - m));
    out[2 * row] = l0 - lse;
    out[2 * row + 1] = l1 - lse;
}

// ---------------- host driver ----------------
static inline int cdiv(long a, long b) { return (int)((a + b - 1) / b); }

static void run_bn_stats(const float* X, int M, int F, float* stats) {
    float* colsum = stats;
    float* colsq = stats + 512;
    float* mean = stats + 1024;
    float* rstd = stats + 1536;
    zero_kernel<<<4, 256>>>(stats, 1024);
    int grid = M < 1184 ? M : 1184;
    bn_partial<<<grid, 256>>>(X, M, F, colsum, colsq);
    bn_finalize<<<cdiv(F, 128), 128>>>(M, F, colsum, colsq, mean, rstd);
}
static void run_bn(float* X, int M, int F, float* stats) {
    run_bn_stats(X, M, F, stats);
    long total4 = (long)M * F / 4;
    bn_apply_relu4<<<cdiv(total4, 256), 256>>>((float4*)X, total4, F / 4,
                                               stats + 1024, stats + 1536);
}

static void gemm(const float* A, const float* B, float* C, int M, int N, int K, int lda,
                 long sA = 0, long sB = 0, long sC = 0, int z = 1, int accum = 0) {
    dim3 grid(cdiv(N, 128), cdiv(M, 128), z);
    sgemm128<<<grid, 256>>>(A, B, C, M, N, K, lda, sA, sB, sC, accum);
}

extern "C" void kernel_launch(void* const* d_in, const int* in_sizes, int n_in,
                              void* d_out, int out_size) {
    const float* fp_data = (const float*)d_in[0];
    const float* mol_x   = (const float*)d_in[1];
    const int*   mol_batch = (const int*)d_in[2];
    const int*   mol_ei  = (const int*)d_in[3];
    const int*   kg_ei   = (const int*)d_in[4];
    const int*   kg_et   = (const int*)d_in[5];
    const float* fp_w1   = (const float*)d_in[6];
    const float* fp_w2   = (const float*)d_in[8];
    const float* gcn_w1  = (const float*)d_in[10];
    const float* gcn_w2  = (const float*)d_in[12];
    const float* att_w1  = (const float*)d_in[14];
    const float* att_b1  = (const float*)d_in[15];
    const float* att_w2  = (const float*)d_in[16];
    const float* gene_emb = (const float*)d_in[17];
    const float* rg_w1   = (const float*)d_in[18];
    const float* rg_root1 = (const float*)d_in[19];
    const float* rg_w2   = (const float*)d_in[21];
    const float* rg_root2 = (const float*)d_in[22];
    const float* lin1_w  = (const float*)d_in[24];
    const float* lin2_w  = (const float*)d_in[26];
    const float* lin2_b  = (const float*)d_in[27];
    float* out = (float*)d_out;

    float *h1, *fpb, *bufA, *bufB, *bufC, *dinv, *pool, *xkg, *hr, *agg, *x3, *stats;
    int *hist_mol, *base_mol, *off_mol, *ssrc_mol, *hist_kg, *base_kg, *off_kg, *ssrc_kg;
    cudaGetSymbolAddress((void**)&h1, g_h1);
    cudaGetSymbolAddress((void**)&fpb, g_fp);
    cudaGetSymbolAddress((void**)&bufA, g_bufA);
    cudaGetSymbolAddress((void**)&bufB, g_bufB);
    cudaGetSymbolAddress((void**)&bufC, g_bufC);
    cudaGetSymbolAddress((void**)&dinv, g_dinv);
    cudaGetSymbolAddress((void**)&pool, g_pool);
    cudaGetSymbolAddress((void**)&xkg, g_xkg);
    cudaGetSymbolAddress((void**)&hr, g_hr);
    cudaGetSymbolAddress((void**)&agg, g_agg);
    cudaGetSymbolAddress((void**)&x3, g_x3);
    cudaGetSymbolAddress((void**)&stats, g_stats);
    cudaGetSymbolAddress((void**)&hist_mol, g_hist_mol);
    cudaGetSymbolAddress((void**)&base_mol, g_base_mol);
    cudaGetSymbolAddress((void**)&off_mol, g_off_mol);
    cudaGetSymbolAddress((void**)&ssrc_mol, g_ssrc_mol);
    cudaGetSymbolAddress((void**)&hist_kg, g_hist_kg);
    cudaGetSymbolAddress((void**)&base_kg, g_base_kg);
    cudaGetSymbolAddress((void**)&off_kg, g_off_kg);
    cudaGetSymbolAddress((void**)&ssrc_kg, g_ssrc_kg);

    const int* msrc = mol_ei;
    const int* mdst = mol_ei + E_MOL_C;
    const int* ksrc = kg_ei;
    const int* kdst = kg_ei + E_KG_C;

    // ---- CSR build: mol graph (by dst) and KG graph (by dst*8+etype) ----
    zero_int<<<cdiv(N_MOL, 256), 256>>>(hist_mol, N_MOL);
    hist_mol_k<<<cdiv(E_MOL_C, 256), 256>>>(hist_mol, mdst, E_MOL_C);
    scan_excl<<<1, 1024>>>(hist_mol, base_mol, off_mol, N_MOL);
    dinv_k<<<cdiv(N_MOL, 256), 256>>>(dinv, hist_mol, N_MOL);
    reorder_mol<<<cdiv(E_MOL_C, 256), 256>>>(msrc, mdst, off_mol, ssrc_mol, E_MOL_C);

    zero_int<<<cdiv(NKEY_KG, 256), 256>>>(hist_kg, NKEY_KG);
    hist_kg_k<<<cdiv(E_KG_C, 256), 256>>>(hist_kg, kdst, kg_et, E_KG_C);
    scan_excl<<<1, 1024>>>(hist_kg, base_kg, off_kg, NKEY_KG);
    reorder_kg<<<cdiv(E_KG_C, 256), 256>>>(ksrc, kdst, kg_et, off_kg, ssrc_kg, E_KG_C);

    // ---- fingerprint MLP branch (biases cancel under BN); split-K z=4 ----
    zero4_kernel<<<cdiv((long)N_DRUGS * MLP_H / 4, 256), 256>>>((float4*)h1, (long)N_DRUGS * MLP_H / 4);
    gemm(fp_data, fp_w1, h1, N_DRUGS, MLP_H, MLP_IN / 4, MLP_IN,
         MLP_IN / 4, (long)(MLP_IN / 4) * MLP_H, 0, 4, 2);
    run_bn(h1, N_DRUGS, MLP_H, stats);
    zero4_kernel<<<cdiv((long)N_DRUGS * DFEAT / 4, 256), 256>>>((float4*)fpb, (long)N_DRUGS * DFEAT / 4);
    gemm(h1, fp_w2, fpb, N_DRUGS, DFEAT, MLP_H / 4, MLP_H,
         MLP_H / 4, (long)(MLP_H / 4) * DFEAT, 0, 4, 2);
    run_bn(fpb, N_DRUGS, DFEAT, stats);

    // ---- molecular GCN branch (aggregate-then-transform, CSR, no atomics) ----
    gcn_agg<<<N_MOL, GCN_IN>>>(mol_x, ssrc_mol, base_mol, dinv, bufA, GCN_IN);
    gemm(bufA, gcn_w1, bufB, N_MOL, GCN_H, GCN_IN, GCN_IN);
    run_bn(bufB, N_MOL, GCN_H, stats);

    gcn_agg<<<N_MOL, GCN_H>>>(bufB, ssrc_mol, base_mol, dinv, bufC, GCN_H);
    gemm(bufC, gcn_w2, bufA, N_MOL, DFEAT, GCN_H, GCN_H);
    // stats on raw conv2 output, then fused BN+relu+mean-pool
    run_bn_stats(bufA, N_MOL, DFEAT, stats);
    bn_pool<<<N_DRUGS, 256>>>(bufA, mol_batch, stats + 1024, stats + 1536, pool);

    // ---- attention fusion -> xkg[0:N_DRUGS], beta -> out tail ----
    att_kernel<<<N_DRUGS, 128>>>(pool, fpb, att_w1, att_b1, att_w2, xkg, out + N_KG * 2);
    copy_kernel<<<cdiv((long)N_GENE * DFEAT / 4, 256), 256>>>(
        (float4*)(xkg + (long)N_DRUGS * DFEAT), (const float4*)gene_emb, (long)N_GENE * DFEAT / 4);

    // ---- RGCN layer 1: CSR aggregate into AGG [N_KG, 2048] (no zero, no atomics) ----
    rgcn_agg1<<<N_KG, 256>>>(xkg, ssrc_kg, base_kg, hr);
    gemm(xkg, rg_root1, agg, N_KG, DIM1, DFEAT, DFEAT);          // agg = x @ root1
    gemm(hr, rg_w1, agg, N_KG, DIM1, 256, 2048,
         256, (long)256 * DIM1, 0, 8, 2);                        // agg += AGG @ W_r (split-K)
    run_bn(agg, N_KG, DIM1, stats);

    // ---- RGCN layer 2: transform-first (batched), CSR gather-add into xkg ----
    gemm(agg, rg_w2, hr, N_KG, DIM2, DIM1, DIM1,
         0, (long)DIM1 * DIM2, (long)N_KG * DIM2, R_REL, 0);
    gemm(agg, rg_root2, xkg, N_KG, DIM2, DIM1, DIM1);
    rgcn_agg2<<<N_KG, 128>>>(hr, ssrc_kg, base_kg, xkg);
    run_bn(xkg, N_KG, DIM2, stats);

    // ---- lin1 + bn + relu ----
    gemm(xkg, lin1_w, x3, N_KG, DIM3, DIM2, DIM2);
    run_bn(x3, N_KG, DIM3, stats);

    // ---- lin2 + log_softmax ----
    lin2_k<<<cdiv(N_KG, 128), 128>>>(x3, lin2_w, lin2_b, out);
}